// round 10
// baseline (speedup 1.0000x reference)
#include <cuda_runtime.h>
#include <cuda_fp16.h>
#include <cstdint>
#include <math.h>

#define T_SEQ   2048
#define C_EMB   4096
#define QKV_N   6144
#define FFN_N   11008
#define N_HEAD_ 32

// ---------------- scratch (static device globals; allocation-free) ----------------
__device__ float g_scaling[T_SEQ * C_EMB];
__device__ float g_scale_t[N_HEAD_ * T_SEQ];
__device__ float g_resid[T_SEQ * C_EMB];
__device__ float g_gate[T_SEQ * FFN_N];

__device__ __half g_qkvh[T_SEQ * QKV_N];
__device__ __half g_n1[T_SEQ * C_EMB];
__device__ __half g_n2[T_SEQ * C_EMB];
__device__ __half g_y[T_SEQ * C_EMB];
__device__ __half g_hb[T_SEQ * FFN_N];
// fp16 attention operands (roped / scaled)
__device__ __half g_qh[N_HEAD_ * T_SEQ * 128];
__device__ __half g_kh[8 * T_SEQ * 128];
__device__ __half g_vh[8 * T_SEQ * 128];

// ---------------- small helpers ----------------
__device__ __forceinline__ uint32_t smem_u32(const void* p) {
    return (uint32_t)__cvta_generic_to_shared(p);
}
__device__ __forceinline__ uint32_t pack_h2(__half a, __half b) {
    __half2 p; p.x = a; p.y = b;
    return *(uint32_t*)&p;
}
__device__ __forceinline__ uint32_t pack_f2h(float a, float b) {
    return pack_h2(__float2half_rn(a), __float2half_rn(b));
}
__device__ __forceinline__ void cp_async16(void* smem_ptr, const void* gptr) {
    unsigned s = (unsigned)__cvta_generic_to_shared(smem_ptr);
    asm volatile("cp.async.cg.shared.global [%0], [%1], 16;" :: "r"(s), "l"(gptr));
}
#define CP_COMMIT() asm volatile("cp.async.commit_group;" ::: "memory")

#define LDSM4(r0, r1, r2, r3, addr) \
    asm volatile("ldmatrix.sync.aligned.m8n8.x4.shared.b16 {%0,%1,%2,%3}, [%4];" \
        : "=r"(r0), "=r"(r1), "=r"(r2), "=r"(r3) : "r"(addr))
#define LDSM4T(r0, r1, r2, r3, addr) \
    asm volatile("ldmatrix.sync.aligned.m8n8.x4.trans.shared.b16 {%0,%1,%2,%3}, [%4];" \
        : "=r"(r0), "=r"(r1), "=r"(r2), "=r"(r3) : "r"(addr))

__device__ __forceinline__ void mma_fp16(float* d, const uint32_t* a, uint32_t b0, uint32_t b1) {
    asm volatile(
        "mma.sync.aligned.m16n8k16.row.col.f32.f16.f16.f32 "
        "{%0,%1,%2,%3},{%4,%5,%6,%7},{%8,%9},{%0,%1,%2,%3};"
        : "+f"(d[0]), "+f"(d[1]), "+f"(d[2]), "+f"(d[3])
        : "r"(a[0]), "r"(a[1]), "r"(a[2]), "r"(a[3]), "r"(b0), "r"(b1));
}

// ---------------- RMSNorm (fp32 in -> fp16 out) ----------------
__global__ __launch_bounds__(256) void rmsnorm_h(const float* __restrict__ x,
                                                 const float* __restrict__ w,
                                                 __half* __restrict__ o) {
    const long row = blockIdx.x;
    const float* xr = x + row * C_EMB;
    const int tid = threadIdx.x;

    float4 v[4];
    float ss = 0.f;
#pragma unroll
    for (int i = 0; i < 4; i++) {
        v[i] = *(const float4*)(xr + tid * 4 + i * 1024);
        ss += v[i].x * v[i].x + v[i].y * v[i].y + v[i].z * v[i].z + v[i].w * v[i].w;
    }
#pragma unroll
    for (int off = 16; off; off >>= 1) ss += __shfl_xor_sync(0xffffffffu, ss, off);
    __shared__ float red[8];
    if ((tid & 31) == 0) red[tid >> 5] = ss;
    __syncthreads();
    float tot = red[0] + red[1] + red[2] + red[3] + red[4] + red[5] + red[6] + red[7];
    const float inv = rsqrtf(tot * (1.f / 4096.f) + 1e-5f);
#pragma unroll
    for (int i = 0; i < 4; i++) {
        float4 wv = *(const float4*)(w + tid * 4 + i * 1024);
        const long off = row * C_EMB + tid * 4 + i * 1024;
        uint2 ou = {pack_f2h(v[i].x * inv * wv.x, v[i].y * inv * wv.y),
                    pack_f2h(v[i].z * inv * wv.z, v[i].w * inv * wv.w)};
        *(uint2*)(o + off) = ou;
    }
}

// ---------------- fp16 mma GEMM, fp32 B with inline convert ----------------
// C[M,N] = A[M,K](fp16) * W[N,K](fp32)^T.  Tile 128x128, BK=64, 3-stage ring.
// A via cp.async; B via LDG fp32 (2 stages ahead) -> CVT pack -> STS fp16 (1 stage ahead).
// EPI: 0 none, 1 relu(+bias), 2 +extra, 3 silu(extra)*acc.  OUT: 0 fp32 C, 1 fp16 Chalf.
#define STAGE_BYTES 32768
#define GEMM_SMEM (3 * STAGE_BYTES)

__device__ __forceinline__ void stageA(char* st, const __half* __restrict__ A,
                                       long bm, long K, int k0, int tid) {
    const int row = tid >> 1;
    const int cb = (tid & 1) * 4;
    const char* src = (const char*)(A + (bm + row) * K + k0);
#pragma unroll
    for (int c = 0; c < 4; c++) {
        const int chunk = cb + c;
        const int sw = row * 128 + ((chunk ^ (row & 7)) << 4);
        cp_async16(st + sw, src + chunk * 16);
    }
}

// load 32 consecutive fp32 B values, convert+pack to 16 uint32 (fp16x2)
__device__ __forceinline__ void ldgB(const float* __restrict__ B, long bn, long K,
                                     int k0, int tid, uint32_t* held) {
    const int row = tid >> 1;
    const int half = tid & 1;
    const float* p = B + (bn + row) * K + k0 + half * 32;
#pragma unroll
    for (int c = 0; c < 8; ++c) {
        const float4 v = *(const float4*)(p + c * 4);
        held[c * 2]     = pack_f2h(v.x, v.y);
        held[c * 2 + 1] = pack_f2h(v.z, v.w);
    }
}

__device__ __forceinline__ void stsB(char* st, const uint32_t* held, int tid) {
    const int row = tid >> 1;
    const int cb = (tid & 1) * 4;
#pragma unroll
    for (int c = 0; c < 4; ++c) {
        const int chunk = cb + c;
        const int sw = row * 128 + ((chunk ^ (row & 7)) << 4);
        *(uint4*)(st + 16384 + sw) = *(const uint4*)(held + c * 4);
    }
}

template <int EPI, int OUT>
__global__ __launch_bounds__(256, 2)
void hgemm32(const __half* __restrict__ A, const float* __restrict__ B,
             float* __restrict__ C, __half* __restrict__ Chalf,
             int M, int N, int K,
             const float* __restrict__ extra, const float* __restrict__ bias) {
    extern __shared__ __align__(1024) char sm[];
    const uint32_t sbase = smem_u32(sm);

    const int tid  = threadIdx.x;
    const int warp = tid >> 5;
    const int lane = tid & 31;
    const long bm = (long)blockIdx.y * 128;
    const long bn = (long)blockIdx.x * 128;
    const int wm = (warp & 1) * 64;
    const int wn = (warp >> 1) * 32;

    const int ar = (lane & 7) + ((lane >> 3) & 1) * 8;
    const int ac = lane >> 4;
    const int br = (lane & 7) + ((lane >> 4) & 1) * 8;
    const int bc = (lane >> 3) & 1;
    const int xr = lane & 7;

    float acc[4][4][4];
#pragma unroll
    for (int mt = 0; mt < 4; mt++)
#pragma unroll
        for (int nt = 0; nt < 4; nt++)
#pragma unroll
            for (int u = 0; u < 4; u++) acc[mt][nt][u] = 0.f;

    const int steps = K >> 6;
    uint32_t heldB[16];

    // prologue: B0 staged immediately; B1 loaded into held regs; A0, A1 via cp.async
    ldgB(B, bn, K, 0, tid, heldB);
    stsB(sm, heldB, tid);
    ldgB(B, bn, K, 64, tid, heldB);
    stageA(sm, A, bm, K, 0, tid);  CP_COMMIT();
    stageA(sm + STAGE_BYTES, A, bm, K, 64, tid); CP_COMMIT();

    for (int s = 0; s < steps; ++s) {
        const int buf = s % 3;
        if (s + 1 < steps) { asm volatile("cp.async.wait_group 1;" ::: "memory"); }
        else               { asm volatile("cp.async.wait_group 0;" ::: "memory"); }
        __syncthreads();
        if (s + 1 < steps) stsB(sm + ((s + 1) % 3) * STAGE_BYTES, heldB, tid);
        if (s + 2 < steps) {
            ldgB(B, bn, K, (s + 2) * 64, tid, heldB);
            stageA(sm + ((s + 2) % 3) * STAGE_BYTES, A, bm, K, (s + 2) * 64, tid);
            CP_COMMIT();
        }
        const uint32_t st = sbase + buf * STAGE_BYTES;
        const uint32_t baseA = st + (wm + ar) * 128;
        const uint32_t baseB = st + 16384 + (wn + br) * 128;

#pragma unroll
        for (int kc = 0; kc < 4; ++kc) {
            const uint32_t aoff = ((((kc << 1) + ac) ^ xr) << 4);
            const uint32_t boff = ((((kc << 1) + bc) ^ xr) << 4);
            uint32_t Af[4][4];
#pragma unroll
            for (int mt = 0; mt < 4; ++mt)
                LDSM4(Af[mt][0], Af[mt][1], Af[mt][2], Af[mt][3], baseA + mt * 2048 + aoff);
            uint32_t Bf[2][4];
#pragma unroll
            for (int hf = 0; hf < 2; ++hf)
                LDSM4(Bf[hf][0], Bf[hf][1], Bf[hf][2], Bf[hf][3], baseB + hf * 2048 + boff);
#pragma unroll
            for (int mt = 0; mt < 4; ++mt)
#pragma unroll
                for (int nt = 0; nt < 4; ++nt) {
                    const int hf = nt >> 1, od = nt & 1;
                    mma_fp16(acc[mt][nt], Af[mt], Bf[hf][od * 2], Bf[hf][od * 2 + 1]);
                }
        }
        __syncthreads();
    }

    const int gi = lane >> 2;
    const int ci = lane & 3;
#pragma unroll
    for (int mt = 0; mt < 4; ++mt) {
        const long row  = bm + wm + mt * 16 + gi;
        const long row2 = row + 8;
#pragma unroll
        for (int nt = 0; nt < 4; ++nt) {
            const long col = bn + wn + nt * 8 + ci * 2;
            float v[4] = {acc[mt][nt][0], acc[mt][nt][1], acc[mt][nt][2], acc[mt][nt][3]};
            if (EPI == 1) {
                const float b0 = bias[col], b1 = bias[col + 1];
                v[0] = fmaxf(v[0] + b0, 0.f); v[1] = fmaxf(v[1] + b1, 0.f);
                v[2] = fmaxf(v[2] + b0, 0.f); v[3] = fmaxf(v[3] + b1, 0.f);
            } else if (EPI == 2) {
                const float2 e0 = *(const float2*)(extra + row * N + col);
                const float2 e1 = *(const float2*)(extra + row2 * N + col);
                v[0] += e0.x; v[1] += e0.y; v[2] += e1.x; v[3] += e1.y;
            } else if (EPI == 3) {
                const float2 g0 = *(const float2*)(extra + row * N + col);
                const float2 g1 = *(const float2*)(extra + row2 * N + col);
                v[0] *= g0.x / (1.f + __expf(-g0.x));
                v[1] *= g0.y / (1.f + __expf(-g0.y));
                v[2] *= g1.x / (1.f + __expf(-g1.x));
                v[3] *= g1.y / (1.f + __expf(-g1.y));
            }
            if (OUT == 0) {
                float2 o0 = {v[0], v[1]}, o1 = {v[2], v[3]};
                *(float2*)(C + row * N + col)  = o0;
                *(float2*)(C + row2 * N + col) = o1;
            } else {
                *(uint32_t*)(Chalf + row * N + col)  = pack_f2h(v[0], v[1]);
                *(uint32_t*)(Chalf + row2 * N + col) = pack_f2h(v[2], v[3]);
            }
        }
    }
}

// ---------------- scale_t[h][t] = mean_d scaling[t][h*128+d] ----------------
__global__ __launch_bounds__(256) void scale_mean_kernel(const float* __restrict__ scaling,
                                                         float* __restrict__ scale_t) {
    const int wid = (blockIdx.x * 256 + threadIdx.x) >> 5;
    const int lane = threadIdx.x & 31;
    const int t = wid >> 5;
    const int h = wid & 31;
    const float4 v = *(const float4*)(scaling + (long)t * C_EMB + h * 128 + lane * 4);
    float s = v.x + v.y + v.z + v.w;
#pragma unroll
    for (int o = 16; o; o >>= 1) s += __shfl_xor_sync(0xffffffffu, s, o);
    if (lane == 0) scale_t[h * T_SEQ + t] = s * (1.f / 128.f);
}

// ---------------- qkv_prep: rope + q prescale (incl. log2e) + fp16 Q/K/V planes ----------------
__global__ __launch_bounds__(128) void qkv_prep(const __half* __restrict__ qkv,
                                                const float* __restrict__ cosb,
                                                const float* __restrict__ sinb,
                                                const float* __restrict__ scale_t,
                                                __half* __restrict__ qh,
                                                __half* __restrict__ kh,
                                                __half* __restrict__ vh) {
    const int t = blockIdx.x;
    const int g = blockIdx.y;
    const int d = threadIdx.x;
    const float c = cosb[t * 128 + d];
    const float s = sinb[t * 128 + d];
    const float sfl = 0.08838834764831845f * 1.4426950408889634f;  // sf * log2(e)
    const __half* base = qkv + (long)t * QKV_N + g * 768;

#pragma unroll
    for (int slot = 0; slot < 4; ++slot) {
        const __half* p = base + slot * 128;
        const float xd = __half2float(p[d]);
        const float xo = __half2float(p[d ^ 64]);
        const float rot = (d < 64) ? -xo : xo;
        const int h = g * 4 + slot;
        const float q = (xd * c + rot * s) * sfl * scale_t[h * T_SEQ + t];
        qh[((long)h * T_SEQ + t) * 128 + d] = __float2half_rn(q);
    }
    {
        const __half* p = base + 4 * 128;
        const float xd = __half2float(p[d]);
        const float xo = __half2float(p[d ^ 64]);
        const float rot = (d < 64) ? -xo : xo;
        kh[((long)g * T_SEQ + t) * 128 + d] = __float2half_rn(xd * c + rot * s);
    }
    vh[((long)g * T_SEQ + t) * 128 + d] = base[5 * 128 + d];
}

// ---------------- flash attention on fp16 mma (FA2-style, non-causal, exp2 softmax) ----------------
#define FL_QS     0
#define FL_STAGE0 32768
#define FL_STAGEB 32768
#define FLASH_SMEM (32768 + 2 * 32768)

__global__ __launch_bounds__(256, 1)
void flash_mma(const __half* __restrict__ qh, const __half* __restrict__ kh,
               const __half* __restrict__ vh, __half* __restrict__ y) {
    extern __shared__ __align__(1024) char sm[];
    const uint32_t sbase = smem_u32(sm);

    const int tid  = threadIdx.x;
    const int warp = tid >> 5;
    const int lane = tid & 31;
    const int qb = blockIdx.x;
    const int h  = blockIdx.y;
    const int g  = h >> 2;

    // --- load Q tile (128 rows x 128 halves), swizzled ---
    {
        const int row = tid >> 1;
        const int cb = (tid & 1) * 8;
        const char* src = (const char*)(qh + ((long)h * T_SEQ + qb * 128 + row) * 128);
#pragma unroll
        for (int c = 0; c < 8; ++c) {
            const int chunk = cb + c;
            const int sw = row * 256 + ((chunk ^ (row & 7)) << 4);
            cp_async16(sm + FL_QS + sw, src + chunk * 16);
        }
        CP_COMMIT();
    }
    // --- stage 0 K/V ---
    {
        const int row = tid >> 2;
        const int cb = (tid & 3) * 4;
        const char* srcK = (const char*)(kh + ((long)g * T_SEQ + row) * 128);
        const char* srcV = (const char*)(vh + ((long)g * T_SEQ + row) * 128);
#pragma unroll
        for (int c = 0; c < 4; ++c) {
            const int chunk = cb + c;
            const int sw = row * 256 + ((chunk ^ (row & 7)) << 4);
            cp_async16(sm + FL_STAGE0 + sw, srcK + chunk * 16);
            cp_async16(sm + FL_STAGE0 + 16384 + sw, srcV + chunk * 16);
        }
        CP_COMMIT();
    }

    asm volatile("cp.async.wait_group 1;" ::: "memory");
    __syncthreads();

    const int ar = (lane & 7) + ((lane >> 3) & 1) * 8;
    const int ac = lane >> 4;
    uint32_t Qf[8][4];
#pragma unroll
    for (int kb = 0; kb < 8; ++kb) {
        const int qrow = warp * 16 + ar;
        const uint32_t addr = sbase + FL_QS + qrow * 256 + ((((kb << 1) + ac) ^ (qrow & 7)) << 4);
        LDSM4(Qf[kb][0], Qf[kb][1], Qf[kb][2], Qf[kb][3], addr);
    }

    const int br = (lane & 7) + ((lane >> 4) & 1) * 8;
    const int bc = (lane >> 3) & 1;
    const int vr = (lane & 7) + ((lane >> 3) & 1) * 8;
    const int vc = lane >> 4;

    float acc[16][4];
#pragma unroll
    for (int dn = 0; dn < 16; ++dn)
#pragma unroll
        for (int u = 0; u < 4; ++u) acc[dn][u] = 0.f;
    float mrow[2] = {-1e30f, -1e30f};
    float lrow[2] = {0.f, 0.f};

    for (int kt = 0; kt < 32; ++kt) {
        asm volatile("cp.async.wait_group 0;" ::: "memory");
        __syncthreads();
        if (kt + 1 < 32) {
            const int row = tid >> 2;
            const int cb = (tid & 3) * 4;
            char* st = sm + FL_STAGE0 + ((kt + 1) & 1) * FL_STAGEB;
            const char* srcK = (const char*)(kh + ((long)g * T_SEQ + (kt + 1) * 64 + row) * 128);
            const char* srcV = (const char*)(vh + ((long)g * T_SEQ + (kt + 1) * 64 + row) * 128);
#pragma unroll
            for (int c = 0; c < 4; ++c) {
                const int chunk = cb + c;
                const int sw = row * 256 + ((chunk ^ (row & 7)) << 4);
                cp_async16(st + sw, srcK + chunk * 16);
                cp_async16(st + 16384 + sw, srcV + chunk * 16);
            }
            CP_COMMIT();
        }
        const uint32_t Ks = sbase + FL_STAGE0 + (kt & 1) * FL_STAGEB;
        const uint32_t Vs = Ks + 16384;

        float sacc[8][4];
#pragma unroll
        for (int j = 0; j < 8; ++j)
#pragma unroll
            for (int u = 0; u < 4; ++u) sacc[j][u] = 0.f;
#pragma unroll
        for (int kb = 0; kb < 8; ++kb) {
            uint32_t Bf[4][4];
#pragma unroll
            for (int n16 = 0; n16 < 4; ++n16) {
                const int krow = n16 * 16 + br;
                const uint32_t addr = Ks + krow * 256 + ((((kb << 1) + bc) ^ (krow & 7)) << 4);
                LDSM4(Bf[n16][0], Bf[n16][1], Bf[n16][2], Bf[n16][3], addr);
            }
#pragma unroll
            for (int nt = 0; nt < 8; ++nt)
                mma_fp16(sacc[nt], Qf[kb], Bf[nt >> 1][(nt & 1) * 2], Bf[nt >> 1][(nt & 1) * 2 + 1]);
        }

        // online softmax in exp2 domain (log2e folded into Q prescale)
#pragma unroll
        for (int rh = 0; rh < 2; ++rh) {
            float tmax = -1e30f;
#pragma unroll
            for (int j = 0; j < 8; ++j)
                tmax = fmaxf(tmax, fmaxf(sacc[j][rh * 2], sacc[j][rh * 2 + 1]));
            tmax = fmaxf(tmax, __shfl_xor_sync(0xffffffffu, tmax, 1));
            tmax = fmaxf(tmax, __shfl_xor_sync(0xffffffffu, tmax, 2));
            const float mnew = fmaxf(mrow[rh], tmax);
            const float corr = exp2f(mrow[rh] - mnew);
            float psum = 0.f;
#pragma unroll
            for (int j = 0; j < 8; ++j) {
                const float p0 = exp2f(sacc[j][rh * 2] - mnew);
                const float p1 = exp2f(sacc[j][rh * 2 + 1] - mnew);
                sacc[j][rh * 2] = p0;
                sacc[j][rh * 2 + 1] = p1;
                psum += p0 + p1;
            }
            psum += __shfl_xor_sync(0xffffffffu, psum, 1);
            psum += __shfl_xor_sync(0xffffffffu, psum, 2);
            lrow[rh] = lrow[rh] * corr + psum;
            mrow[rh] = mnew;
#pragma unroll
            for (int dn = 0; dn < 16; ++dn) {
                acc[dn][rh * 2] *= corr;
                acc[dn][rh * 2 + 1] *= corr;
            }
        }

        uint32_t Pa[4][4];
#pragma unroll
        for (int t = 0; t < 4; ++t) {
            Pa[t][0] = pack_f2h(sacc[2 * t][0], sacc[2 * t][1]);
            Pa[t][1] = pack_f2h(sacc[2 * t][2], sacc[2 * t][3]);
            Pa[t][2] = pack_f2h(sacc[2 * t + 1][0], sacc[2 * t + 1][1]);
            Pa[t][3] = pack_f2h(sacc[2 * t + 1][2], sacc[2 * t + 1][3]);
        }

#pragma unroll
        for (int t = 0; t < 4; ++t) {
            const int vrow = t * 16 + vr;
#pragma unroll
            for (int dn16 = 0; dn16 < 8; ++dn16) {
                uint32_t Vt[4];
                const uint32_t addr = Vs + vrow * 256 + ((((dn16 << 1) + vc) ^ (vrow & 7)) << 4);
                LDSM4T(Vt[0], Vt[1], Vt[2], Vt[3], addr);
                mma_fp16(acc[dn16 * 2],     Pa[t], Vt[0], Vt[1]);
                mma_fp16(acc[dn16 * 2 + 1], Pa[t], Vt[2], Vt[3]);
            }
        }
    }

    const int gi = lane >> 2;
    const int ci = lane & 3;
    const float il0 = 1.f / lrow[0];
    const float il1 = 1.f / lrow[1];
    const long row0 = (long)qb * 128 + warp * 16 + gi;
    const long row1 = row0 + 8;
#pragma unroll
    for (int dn = 0; dn < 16; ++dn) {
        const long col = h * 128 + dn * 8 + ci * 2;
        *(uint32_t*)(y + row0 * C_EMB + col) = pack_f2h(acc[dn][0] * il0, acc[dn][1] * il0);
        *(uint32_t*)(y + row1 * C_EMB + col) = pack_f2h(acc[dn][2] * il1, acc[dn][3] * il1);
    }
}

// ---------------- host launcher ----------------
extern "C" void kernel_launch(void* const* d_in, const int* in_sizes, int n_in,
                              void* d_out, int out_size) {
    const float* x       = (const float*)d_in[0];
    const float* cosb    = (const float*)d_in[1];
    const float* sinb    = (const float*)d_in[2];
    const float* norm1_w = (const float*)d_in[3];
    const float* norm2_w = (const float*)d_in[4];
    const float* attn_w  = (const float*)d_in[5];
    const float* proj_w  = (const float*)d_in[6];
    const float* scale_w = (const float*)d_in[7];
    const float* scale_b = (const float*)d_in[8];
    const float* gate_w  = (const float*)d_in[9];
    const float* up_w    = (const float*)d_in[10];
    const float* down_w  = (const float*)d_in[11];
    float* out = (float*)d_out;

    float *scaling, *scale_t, *resid, *gate;
    cudaGetSymbolAddress((void**)&scaling, g_scaling);
    cudaGetSymbolAddress((void**)&scale_t, g_scale_t);
    cudaGetSymbolAddress((void**)&resid, g_resid);
    cudaGetSymbolAddress((void**)&gate, g_gate);

    __half *qkvh, *n1, *n2, *y, *hb, *qh, *kh, *vh;
    cudaGetSymbolAddress((void**)&qkvh, g_qkvh);
    cudaGetSymbolAddress((void**)&n1, g_n1);
    cudaGetSymbolAddress((void**)&n2, g_n2);
    cudaGetSymbolAddress((void**)&y, g_y);
    cudaGetSymbolAddress((void**)&hb, g_hb);
    cudaGetSymbolAddress((void**)&qh, g_qh);
    cudaGetSymbolAddress((void**)&kh, g_kh);
    cudaGetSymbolAddress((void**)&vh, g_vh);

    cudaFuncSetAttribute(flash_mma, cudaFuncAttributeMaxDynamicSharedMemorySize, FLASH_SMEM);
    cudaFuncSetAttribute(hgemm32<0, 0>, cudaFuncAttributeMaxDynamicSharedMemorySize, GEMM_SMEM);
    cudaFuncSetAttribute(hgemm32<0, 1>, cudaFuncAttributeMaxDynamicSharedMemorySize, GEMM_SMEM);
    cudaFuncSetAttribute(hgemm32<1, 0>, cudaFuncAttributeMaxDynamicSharedMemorySize, GEMM_SMEM);
    cudaFuncSetAttribute(hgemm32<2, 0>, cudaFuncAttributeMaxDynamicSharedMemorySize, GEMM_SMEM);
    cudaFuncSetAttribute(hgemm32<3, 1>, cudaFuncAttributeMaxDynamicSharedMemorySize, GEMM_SMEM);

    // n1 = rmsnorm(x, norm1_w) -> fp16
    rmsnorm_h<<<T_SEQ, 256>>>(x, norm1_w, n1);
    // qkv = n1 @ attn_w^T -> fp16 (weights converted inline)
    hgemm32<0, 1><<<dim3(QKV_N / 128, T_SEQ / 128), 256, GEMM_SMEM>>>(
        n1, attn_w, nullptr, qkvh, T_SEQ, QKV_N, C_EMB, nullptr, nullptr);
    // scaling = relu(n1 @ scale_w^T + b) (fp32)
    hgemm32<1, 0><<<dim3(C_EMB / 128, T_SEQ / 128), 256, GEMM_SMEM>>>(
        n1, scale_w, scaling, nullptr, T_SEQ, C_EMB, C_EMB, nullptr, scale_b);
    // per-head score scale
    scale_mean_kernel<<<(T_SEQ * N_HEAD_) / 8, 256>>>(scaling, scale_t);
    // rope + prescale (sf*scale_t*log2e) + fp16 Q/K/V planes
    qkv_prep<<<dim3(T_SEQ, 8), 128>>>(qkvh, cosb, sinb, scale_t, qh, kh, vh);
    // flash attention -> y fp16
    flash_mma<<<dim3(T_SEQ / 128, N_HEAD_), 256, FLASH_SMEM>>>(qh, kh, vh, y);
    // resid = x + y @ proj_w^T (fp32)
    hgemm32<2, 0><<<dim3(C_EMB / 128, T_SEQ / 128), 256, GEMM_SMEM>>>(
        y, proj_w, resid, nullptr, T_SEQ, C_EMB, C_EMB, x, nullptr);
    // n2 = rmsnorm(resid) -> fp16
    rmsnorm_h<<<T_SEQ, 256>>>(resid, norm2_w, n2);
    // gate = n2 @ gate_w^T (fp32)
    hgemm32<0, 0><<<dim3(FFN_N / 128, T_SEQ / 128), 256, GEMM_SMEM>>>(
        n2, gate_w, gate, nullptr, T_SEQ, FFN_N, C_EMB, nullptr, nullptr);
    // hbuf = silu(gate) * (n2 @ up_w^T) -> fp16
    hgemm32<3, 1><<<dim3(FFN_N / 128, T_SEQ / 128), 256, GEMM_SMEM>>>(
        n2, up_w, nullptr, hb, T_SEQ, FFN_N, C_EMB, gate, nullptr);
    // out = resid + hbuf @ down_w^T (fp32)
    hgemm32<2, 0><<<dim3(C_EMB / 128, T_SEQ / 128), 256, GEMM_SMEM>>>(
        hb, down_w, out, nullptr, T_SEQ, C_EMB, FFN_N, resid, nullptr);
}

// round 11
// speedup vs baseline: 1.5210x; 1.5210x over previous
#include <cuda_runtime.h>
#include <cuda_fp16.h>
#include <cstdint>
#include <math.h>

#define T_SEQ   2048
#define C_EMB   4096
#define QKV_N   6144
#define FFN_N   11008
#define N_HEAD_ 32

// ---------------- scratch (static device globals; allocation-free) ----------------
__device__ float g_scaling[T_SEQ * C_EMB];
__device__ float g_scale_t[N_HEAD_ * T_SEQ];
__device__ float g_resid[T_SEQ * C_EMB];
__device__ float g_gate[T_SEQ * FFN_N];

// fp16 operand planes
__device__ __half g_wq[QKV_N * C_EMB];
__device__ __half g_ws[C_EMB * C_EMB];
__device__ __half g_wp[C_EMB * C_EMB];
__device__ __half g_wg[FFN_N * C_EMB];
__device__ __half g_wu[FFN_N * C_EMB];
__device__ __half g_wd[C_EMB * FFN_N];
__device__ __half g_qkvh[T_SEQ * QKV_N];
__device__ __half g_n1[T_SEQ * C_EMB];
__device__ __half g_n2[T_SEQ * C_EMB];
__device__ __half g_y[T_SEQ * C_EMB];
__device__ __half g_hb[T_SEQ * FFN_N];
// fp16 attention operands (roped / scaled)
__device__ __half g_qh[N_HEAD_ * T_SEQ * 128];
__device__ __half g_kh[8 * T_SEQ * 128];
__device__ __half g_vh[8 * T_SEQ * 128];

// ---------------- small helpers ----------------
__device__ __forceinline__ uint32_t smem_u32(const void* p) {
    return (uint32_t)__cvta_generic_to_shared(p);
}
__device__ __forceinline__ uint32_t pack_h2(__half a, __half b) {
    __half2 p; p.x = a; p.y = b;
    return *(uint32_t*)&p;
}
__device__ __forceinline__ uint32_t pack_f2h(float a, float b) {
    return pack_h2(__float2half_rn(a), __float2half_rn(b));
}
__device__ __forceinline__ void cp_async16(void* smem_ptr, const void* gptr) {
    unsigned s = (unsigned)__cvta_generic_to_shared(smem_ptr);
    asm volatile("cp.async.cg.shared.global [%0], [%1], 16;" :: "r"(s), "l"(gptr));
}
#define CP_COMMIT() asm volatile("cp.async.commit_group;" ::: "memory")

#define LDSM4(r0, r1, r2, r3, addr) \
    asm volatile("ldmatrix.sync.aligned.m8n8.x4.shared.b16 {%0,%1,%2,%3}, [%4];" \
        : "=r"(r0), "=r"(r1), "=r"(r2), "=r"(r3) : "r"(addr))
#define LDSM4T(r0, r1, r2, r3, addr) \
    asm volatile("ldmatrix.sync.aligned.m8n8.x4.trans.shared.b16 {%0,%1,%2,%3}, [%4];" \
        : "=r"(r0), "=r"(r1), "=r"(r2), "=r"(r3) : "r"(addr))

__device__ __forceinline__ void mma_fp16(float* d, const uint32_t* a, uint32_t b0, uint32_t b1) {
    asm volatile(
        "mma.sync.aligned.m16n8k16.row.col.f32.f16.f16.f32 "
        "{%0,%1,%2,%3},{%4,%5,%6,%7},{%8,%9},{%0,%1,%2,%3};"
        : "+f"(d[0]), "+f"(d[1]), "+f"(d[2]), "+f"(d[3])
        : "r"(a[0]), "r"(a[1]), "r"(a[2]), "r"(a[3]), "r"(b0), "r"(b1));
}

// ---------------- fp32 -> fp16 convert kernel ----------------
__global__ __launch_bounds__(256) void cvt_kernel(const float* __restrict__ in,
                                                  __half* __restrict__ outp) {
    const long i = ((long)blockIdx.x * 256 + threadIdx.x) * 4;
    const float4 v = *(const float4*)(in + i);
    uint2 o = {pack_f2h(v.x, v.y), pack_f2h(v.z, v.w)};
    *(uint2*)(outp + i) = o;
}

// ---------------- RMSNorm (fp32 in -> fp16 out) ----------------
__global__ __launch_bounds__(256) void rmsnorm_h(const float* __restrict__ x,
                                                 const float* __restrict__ w,
                                                 __half* __restrict__ o) {
    const long row = blockIdx.x;
    const float* xr = x + row * C_EMB;
    const int tid = threadIdx.x;

    float4 v[4];
    float ss = 0.f;
#pragma unroll
    for (int i = 0; i < 4; i++) {
        v[i] = *(const float4*)(xr + tid * 4 + i * 1024);
        ss += v[i].x * v[i].x + v[i].y * v[i].y + v[i].z * v[i].z + v[i].w * v[i].w;
    }
#pragma unroll
    for (int off = 16; off; off >>= 1) ss += __shfl_xor_sync(0xffffffffu, ss, off);
    __shared__ float red[8];
    if ((tid & 31) == 0) red[tid >> 5] = ss;
    __syncthreads();
    float tot = red[0] + red[1] + red[2] + red[3] + red[4] + red[5] + red[6] + red[7];
    const float inv = rsqrtf(tot * (1.f / 4096.f) + 1e-5f);
#pragma unroll
    for (int i = 0; i < 4; i++) {
        float4 wv = *(const float4*)(w + tid * 4 + i * 1024);
        const long off = row * C_EMB + tid * 4 + i * 1024;
        uint2 ou = {pack_f2h(v[i].x * inv * wv.x, v[i].y * inv * wv.y),
                    pack_f2h(v[i].z * inv * wv.z, v[i].w * inv * wv.w)};
        *(uint2*)(o + off) = ou;
    }
}

// ---------------- fp16 mma GEMM: C[M,N] = A[M,K] * W[N,K]^T ----------------
#define STAGE_BYTES 32768
#define GEMM_SMEM (3 * STAGE_BYTES)

__device__ __forceinline__ void stage_tiles(char* sm, int stg,
        const __half* __restrict__ A, const __half* __restrict__ B,
        long bm, long bn, long K, int k0, int tid) {
    const int row = tid >> 1;
    const int cb = (tid & 1) * 4;
    char* st = sm + stg * STAGE_BYTES;
    const char* srcA = (const char*)(A + (bm + row) * K + k0);
    const char* srcB = (const char*)(B + (bn + row) * K + k0);
#pragma unroll
    for (int c = 0; c < 4; c++) {
        const int chunk = cb + c;
        const int sw = row * 128 + ((chunk ^ (row & 7)) << 4);
        cp_async16(st + sw, srcA + chunk * 16);
        cp_async16(st + 16384 + sw, srcB + chunk * 16);
    }
}

template <int EPI, int OUT>
__global__ __launch_bounds__(256, 2)
void hgemm(const __half* __restrict__ A, const __half* __restrict__ B,
           float* __restrict__ C, __half* __restrict__ Chalf,
           int M, int N, int K,
           const float* __restrict__ extra, const float* __restrict__ bias) {
    extern __shared__ __align__(1024) char sm[];
    const uint32_t sbase = smem_u32(sm);

    const int tid  = threadIdx.x;
    const int warp = tid >> 5;
    const int lane = tid & 31;
    const long bm = (long)blockIdx.y * 128;
    const long bn = (long)blockIdx.x * 128;
    const int wm = (warp & 1) * 64;
    const int wn = (warp >> 1) * 32;

    const int ar = (lane & 7) + ((lane >> 3) & 1) * 8;
    const int ac = lane >> 4;
    const int br = (lane & 7) + ((lane >> 4) & 1) * 8;
    const int bc = (lane >> 3) & 1;
    const int xr = lane & 7;

    float acc[4][4][4];
#pragma unroll
    for (int mt = 0; mt < 4; mt++)
#pragma unroll
        for (int nt = 0; nt < 4; nt++)
#pragma unroll
            for (int u = 0; u < 4; u++) acc[mt][nt][u] = 0.f;

    const int steps = K >> 6;
    stage_tiles(sm, 0, A, B, bm, bn, K, 0, tid);  CP_COMMIT();
    stage_tiles(sm, 1, A, B, bm, bn, K, 64, tid); CP_COMMIT();

    for (int s = 0; s < steps; ++s) {
        const int buf = s % 3;
        if (s + 1 < steps) { asm volatile("cp.async.wait_group 1;" ::: "memory"); }
        else               { asm volatile("cp.async.wait_group 0;" ::: "memory"); }
        __syncthreads();
        if (s + 2 < steps) {
            stage_tiles(sm, (s + 2) % 3, A, B, bm, bn, K, (s + 2) * 64, tid);
            CP_COMMIT();
        }
        const uint32_t st = sbase + buf * STAGE_BYTES;
        const uint32_t baseA = st + (wm + ar) * 128;
        const uint32_t baseB = st + 16384 + (wn + br) * 128;

#pragma unroll
        for (int kc = 0; kc < 4; ++kc) {
            const uint32_t aoff = ((((kc << 1) + ac) ^ xr) << 4);
            const uint32_t boff = ((((kc << 1) + bc) ^ xr) << 4);
            uint32_t Af[4][4];
#pragma unroll
            for (int mt = 0; mt < 4; ++mt)
                LDSM4(Af[mt][0], Af[mt][1], Af[mt][2], Af[mt][3], baseA + mt * 2048 + aoff);
            uint32_t Bf[2][4];
#pragma unroll
            for (int hf = 0; hf < 2; ++hf)
                LDSM4(Bf[hf][0], Bf[hf][1], Bf[hf][2], Bf[hf][3], baseB + hf * 2048 + boff);
#pragma unroll
            for (int mt = 0; mt < 4; ++mt)
#pragma unroll
                for (int nt = 0; nt < 4; ++nt) {
                    const int hf = nt >> 1, od = nt & 1;
                    mma_fp16(acc[mt][nt], Af[mt], Bf[hf][od * 2], Bf[hf][od * 2 + 1]);
                }
        }
        __syncthreads();
    }

    const int gi = lane >> 2;
    const int ci = lane & 3;
#pragma unroll
    for (int mt = 0; mt < 4; ++mt) {
        const long row  = bm + wm + mt * 16 + gi;
        const long row2 = row + 8;
#pragma unroll
        for (int nt = 0; nt < 4; ++nt) {
            const long col = bn + wn + nt * 8 + ci * 2;
            float v[4] = {acc[mt][nt][0], acc[mt][nt][1], acc[mt][nt][2], acc[mt][nt][3]};
            if (EPI == 1) {
                const float b0 = bias[col], b1 = bias[col + 1];
                v[0] = fmaxf(v[0] + b0, 0.f); v[1] = fmaxf(v[1] + b1, 0.f);
                v[2] = fmaxf(v[2] + b0, 0.f); v[3] = fmaxf(v[3] + b1, 0.f);
            } else if (EPI == 2) {
                const float2 e0 = *(const float2*)(extra + row * N + col);
                const float2 e1 = *(const float2*)(extra + row2 * N + col);
                v[0] += e0.x; v[1] += e0.y; v[2] += e1.x; v[3] += e1.y;
            } else if (EPI == 3) {
                const float2 g0 = *(const float2*)(extra + row * N + col);
                const float2 g1 = *(const float2*)(extra + row2 * N + col);
                v[0] *= g0.x / (1.f + __expf(-g0.x));
                v[1] *= g0.y / (1.f + __expf(-g0.y));
                v[2] *= g1.x / (1.f + __expf(-g1.x));
                v[3] *= g1.y / (1.f + __expf(-g1.y));
            }
            if (OUT == 0) {
                float2 o0 = {v[0], v[1]}, o1 = {v[2], v[3]};
                *(float2*)(C + row * N + col)  = o0;
                *(float2*)(C + row2 * N + col) = o1;
            } else {
                *(uint32_t*)(Chalf + row * N + col)  = pack_f2h(v[0], v[1]);
                *(uint32_t*)(Chalf + row2 * N + col) = pack_f2h(v[2], v[3]);
            }
        }
    }
}

// ---------------- scale_t[h][t] = mean_d scaling[t][h*128+d] ----------------
__global__ __launch_bounds__(256) void scale_mean_kernel(const float* __restrict__ scaling,
                                                         float* __restrict__ scale_t) {
    const int wid = (blockIdx.x * 256 + threadIdx.x) >> 5;
    const int lane = threadIdx.x & 31;
    const int t = wid >> 5;
    const int h = wid & 31;
    const float4 v = *(const float4*)(scaling + (long)t * C_EMB + h * 128 + lane * 4);
    float s = v.x + v.y + v.z + v.w;
#pragma unroll
    for (int o = 16; o; o >>= 1) s += __shfl_xor_sync(0xffffffffu, s, o);
    if (lane == 0) scale_t[h * T_SEQ + t] = s * (1.f / 128.f);
}

// ---------------- qkv_prep: rope + q prescale (incl. log2e) + fp16 Q/K/V planes ----------------
__global__ __launch_bounds__(128) void qkv_prep(const __half* __restrict__ qkv,
                                                const float* __restrict__ cosb,
                                                const float* __restrict__ sinb,
                                                const float* __restrict__ scale_t,
                                                __half* __restrict__ qh,
                                                __half* __restrict__ kh,
                                                __half* __restrict__ vh) {
    const int t = blockIdx.x;
    const int g = blockIdx.y;
    const int d = threadIdx.x;
    const float c = cosb[t * 128 + d];
    const float s = sinb[t * 128 + d];
    const float sfl = 0.08838834764831845f * 1.4426950408889634f;  // sf * log2(e)
    const __half* base = qkv + (long)t * QKV_N + g * 768;

#pragma unroll
    for (int slot = 0; slot < 4; ++slot) {
        const __half* p = base + slot * 128;
        const float xd = __half2float(p[d]);
        const float xo = __half2float(p[d ^ 64]);
        const float rot = (d < 64) ? -xo : xo;
        const int h = g * 4 + slot;
        const float q = (xd * c + rot * s) * sfl * scale_t[h * T_SEQ + t];
        qh[((long)h * T_SEQ + t) * 128 + d] = __float2half_rn(q);
    }
    {
        const __half* p = base + 4 * 128;
        const float xd = __half2float(p[d]);
        const float xo = __half2float(p[d ^ 64]);
        const float rot = (d < 64) ? -xo : xo;
        kh[((long)g * T_SEQ + t) * 128 + d] = __float2half_rn(xd * c + rot * s);
    }
    vh[((long)g * T_SEQ + t) * 128 + d] = base[5 * 128 + d];
}

// ---------------- flash attention on fp16 mma (FA2-style, non-causal, exp2 softmax) ----------------
#define FL_QS     0
#define FL_STAGE0 32768
#define FL_STAGEB 32768
#define FLASH_SMEM (32768 + 2 * 32768)

__global__ __launch_bounds__(256, 1)
void flash_mma(const __half* __restrict__ qh, const __half* __restrict__ kh,
               const __half* __restrict__ vh, __half* __restrict__ y) {
    extern __shared__ __align__(1024) char sm[];
    const uint32_t sbase = smem_u32(sm);

    const int tid  = threadIdx.x;
    const int warp = tid >> 5;
    const int lane = tid & 31;
    const int qb = blockIdx.x;
    const int h  = blockIdx.y;
    const int g  = h >> 2;

    // --- load Q tile (128 rows x 128 halves), swizzled ---
    {
        const int row = tid >> 1;
        const int cb = (tid & 1) * 8;
        const char* src = (const char*)(qh + ((long)h * T_SEQ + qb * 128 + row) * 128);
#pragma unroll
        for (int c = 0; c < 8; ++c) {
            const int chunk = cb + c;
            const int sw = row * 256 + ((chunk ^ (row & 7)) << 4);
            cp_async16(sm + FL_QS + sw, src + chunk * 16);
        }
        CP_COMMIT();
    }
    // --- stage 0 K/V ---
    {
        const int row = tid >> 2;
        const int cb = (tid & 3) * 4;
        const char* srcK = (const char*)(kh + ((long)g * T_SEQ + row) * 128);
        const char* srcV = (const char*)(vh + ((long)g * T_SEQ + row) * 128);
#pragma unroll
        for (int c = 0; c < 4; ++c) {
            const int chunk = cb + c;
            const int sw = row * 256 + ((chunk ^ (row & 7)) << 4);
            cp_async16(sm + FL_STAGE0 + sw, srcK + chunk * 16);
            cp_async16(sm + FL_STAGE0 + 16384 + sw, srcV + chunk * 16);
        }
        CP_COMMIT();
    }

    asm volatile("cp.async.wait_group 1;" ::: "memory");
    __syncthreads();

    const int ar = (lane & 7) + ((lane >> 3) & 1) * 8;
    const int ac = lane >> 4;
    uint32_t Qf[8][4];
#pragma unroll
    for (int kb = 0; kb < 8; ++kb) {
        const int qrow = warp * 16 + ar;
        const uint32_t addr = sbase + FL_QS + qrow * 256 + ((((kb << 1) + ac) ^ (qrow & 7)) << 4);
        LDSM4(Qf[kb][0], Qf[kb][1], Qf[kb][2], Qf[kb][3], addr);
    }

    const int br = (lane & 7) + ((lane >> 4) & 1) * 8;
    const int bc = (lane >> 3) & 1;
    const int vr = (lane & 7) + ((lane >> 3) & 1) * 8;
    const int vc = lane >> 4;

    float acc[16][4];
#pragma unroll
    for (int dn = 0; dn < 16; ++dn)
#pragma unroll
        for (int u = 0; u < 4; ++u) acc[dn][u] = 0.f;
    float mrow[2] = {-1e30f, -1e30f};
    float lrow[2] = {0.f, 0.f};

    for (int kt = 0; kt < 32; ++kt) {
        asm volatile("cp.async.wait_group 0;" ::: "memory");
        __syncthreads();
        if (kt + 1 < 32) {
            const int row = tid >> 2;
            const int cb = (tid & 3) * 4;
            char* st = sm + FL_STAGE0 + ((kt + 1) & 1) * FL_STAGEB;
            const char* srcK = (const char*)(kh + ((long)g * T_SEQ + (kt + 1) * 64 + row) * 128);
            const char* srcV = (const char*)(vh + ((long)g * T_SEQ + (kt + 1) * 64 + row) * 128);
#pragma unroll
            for (int c = 0; c < 4; ++c) {
                const int chunk = cb + c;
                const int sw = row * 256 + ((chunk ^ (row & 7)) << 4);
                cp_async16(st + sw, srcK + chunk * 16);
                cp_async16(st + 16384 + sw, srcV + chunk * 16);
            }
            CP_COMMIT();
        }
        const uint32_t Ks = sbase + FL_STAGE0 + (kt & 1) * FL_STAGEB;
        const uint32_t Vs = Ks + 16384;

        float sacc[8][4];
#pragma unroll
        for (int j = 0; j < 8; ++j)
#pragma unroll
            for (int u = 0; u < 4; ++u) sacc[j][u] = 0.f;
#pragma unroll
        for (int kb = 0; kb < 8; ++kb) {
            uint32_t Bf[4][4];
#pragma unroll
            for (int n16 = 0; n16 < 4; ++n16) {
                const int krow = n16 * 16 + br;
                const uint32_t addr = Ks + krow * 256 + ((((kb << 1) + bc) ^ (krow & 7)) << 4);
                LDSM4(Bf[n16][0], Bf[n16][1], Bf[n16][2], Bf[n16][3], addr);
            }
#pragma unroll
            for (int nt = 0; nt < 8; ++nt)
                mma_fp16(sacc[nt], Qf[kb], Bf[nt >> 1][(nt & 1) * 2], Bf[nt >> 1][(nt & 1) * 2 + 1]);
        }

        // online softmax in exp2 domain (log2e folded into Q prescale)
#pragma unroll
        for (int rh = 0; rh < 2; ++rh) {
            float tmax = -1e30f;
#pragma unroll
            for (int j = 0; j < 8; ++j)
                tmax = fmaxf(tmax, fmaxf(sacc[j][rh * 2], sacc[j][rh * 2 + 1]));
            tmax = fmaxf(tmax, __shfl_xor_sync(0xffffffffu, tmax, 1));
            tmax = fmaxf(tmax, __shfl_xor_sync(0xffffffffu, tmax, 2));
            const float mnew = fmaxf(mrow[rh], tmax);
            const float corr = exp2f(mrow[rh] - mnew);
            float psum = 0.f;
#pragma unroll
            for (int j = 0; j < 8; ++j) {
                const float p0 = exp2f(sacc[j][rh * 2] - mnew);
                const float p1 = exp2f(sacc[j][rh * 2 + 1] - mnew);
                sacc[j][rh * 2] = p0;
                sacc[j][rh * 2 + 1] = p1;
                psum += p0 + p1;
            }
            psum += __shfl_xor_sync(0xffffffffu, psum, 1);
            psum += __shfl_xor_sync(0xffffffffu, psum, 2);
            lrow[rh] = lrow[rh] * corr + psum;
            mrow[rh] = mnew;
#pragma unroll
            for (int dn = 0; dn < 16; ++dn) {
                acc[dn][rh * 2] *= corr;
                acc[dn][rh * 2 + 1] *= corr;
            }
        }

        uint32_t Pa[4][4];
#pragma unroll
        for (int t = 0; t < 4; ++t) {
            Pa[t][0] = pack_f2h(sacc[2 * t][0], sacc[2 * t][1]);
            Pa[t][1] = pack_f2h(sacc[2 * t][2], sacc[2 * t][3]);
            Pa[t][2] = pack_f2h(sacc[2 * t + 1][0], sacc[2 * t + 1][1]);
            Pa[t][3] = pack_f2h(sacc[2 * t + 1][2], sacc[2 * t + 1][3]);
        }

#pragma unroll
        for (int t = 0; t < 4; ++t) {
            const int vrow = t * 16 + vr;
#pragma unroll
            for (int dn16 = 0; dn16 < 8; ++dn16) {
                uint32_t Vt[4];
                const uint32_t addr = Vs + vrow * 256 + ((((dn16 << 1) + vc) ^ (vrow & 7)) << 4);
                LDSM4T(Vt[0], Vt[1], Vt[2], Vt[3], addr);
                mma_fp16(acc[dn16 * 2],     Pa[t], Vt[0], Vt[1]);
                mma_fp16(acc[dn16 * 2 + 1], Pa[t], Vt[2], Vt[3]);
            }
        }
    }

    const int gi = lane >> 2;
    const int ci = lane & 3;
    const float il0 = 1.f / lrow[0];
    const float il1 = 1.f / lrow[1];
    const long row0 = (long)qb * 128 + warp * 16 + gi;
    const long row1 = row0 + 8;
#pragma unroll
    for (int dn = 0; dn < 16; ++dn) {
        const long col = h * 128 + dn * 8 + ci * 2;
        *(uint32_t*)(y + row0 * C_EMB + col) = pack_f2h(acc[dn][0] * il0, acc[dn][1] * il0);
        *(uint32_t*)(y + row1 * C_EMB + col) = pack_f2h(acc[dn][2] * il1, acc[dn][3] * il1);
    }
}

// ---------------- host launcher ----------------
extern "C" void kernel_launch(void* const* d_in, const int* in_sizes, int n_in,
                              void* d_out, int out_size) {
    const float* x       = (const float*)d_in[0];
    const float* cosb    = (const float*)d_in[1];
    const float* sinb    = (const float*)d_in[2];
    const float* norm1_w = (const float*)d_in[3];
    const float* norm2_w = (const float*)d_in[4];
    const float* attn_w  = (const float*)d_in[5];
    const float* proj_w  = (const float*)d_in[6];
    const float* scale_w = (const float*)d_in[7];
    const float* scale_b = (const float*)d_in[8];
    const float* gate_w  = (const float*)d_in[9];
    const float* up_w    = (const float*)d_in[10];
    const float* down_w  = (const float*)d_in[11];
    float* out = (float*)d_out;

    float *scaling, *scale_t, *resid, *gate;
    cudaGetSymbolAddress((void**)&scaling, g_scaling);
    cudaGetSymbolAddress((void**)&scale_t, g_scale_t);
    cudaGetSymbolAddress((void**)&resid, g_resid);
    cudaGetSymbolAddress((void**)&gate, g_gate);

    __half *wq, *ws, *wp, *wg, *wu, *wd, *qkvh, *n1, *n2, *y, *hb, *qh, *kh, *vh;
    cudaGetSymbolAddress((void**)&wq, g_wq);
    cudaGetSymbolAddress((void**)&ws, g_ws);
    cudaGetSymbolAddress((void**)&wp, g_wp);
    cudaGetSymbolAddress((void**)&wg, g_wg);
    cudaGetSymbolAddress((void**)&wu, g_wu);
    cudaGetSymbolAddress((void**)&wd, g_wd);
    cudaGetSymbolAddress((void**)&qkvh, g_qkvh);
    cudaGetSymbolAddress((void**)&n1, g_n1);
    cudaGetSymbolAddress((void**)&n2, g_n2);
    cudaGetSymbolAddress((void**)&y, g_y);
    cudaGetSymbolAddress((void**)&hb, g_hb);
    cudaGetSymbolAddress((void**)&qh, g_qh);
    cudaGetSymbolAddress((void**)&kh, g_kh);
    cudaGetSymbolAddress((void**)&vh, g_vh);

    cudaFuncSetAttribute(flash_mma, cudaFuncAttributeMaxDynamicSharedMemorySize, FLASH_SMEM);
    cudaFuncSetAttribute(hgemm<0, 0>, cudaFuncAttributeMaxDynamicSharedMemorySize, GEMM_SMEM);
    cudaFuncSetAttribute(hgemm<0, 1>, cudaFuncAttributeMaxDynamicSharedMemorySize, GEMM_SMEM);
    cudaFuncSetAttribute(hgemm<1, 0>, cudaFuncAttributeMaxDynamicSharedMemorySize, GEMM_SMEM);
    cudaFuncSetAttribute(hgemm<2, 0>, cudaFuncAttributeMaxDynamicSharedMemorySize, GEMM_SMEM);
    cudaFuncSetAttribute(hgemm<3, 1>, cudaFuncAttributeMaxDynamicSharedMemorySize, GEMM_SMEM);

    // weight converts (fp32 -> fp16)
    cvt_kernel<<<(QKV_N * C_EMB) / 1024, 256>>>(attn_w, wq);
    cvt_kernel<<<(C_EMB * C_EMB) / 1024, 256>>>(scale_w, ws);
    cvt_kernel<<<(C_EMB * C_EMB) / 1024, 256>>>(proj_w, wp);
    cvt_kernel<<<(FFN_N * C_EMB) / 1024, 256>>>(gate_w, wg);
    cvt_kernel<<<(FFN_N * C_EMB) / 1024, 256>>>(up_w, wu);
    cvt_kernel<<<(C_EMB * FFN_N) / 1024, 256>>>(down_w, wd);

    // n1 = rmsnorm(x, norm1_w) -> fp16
    rmsnorm_h<<<T_SEQ, 256>>>(x, norm1_w, n1);
    // qkv = n1 @ attn_w^T -> fp16 directly
    hgemm<0, 1><<<dim3(QKV_N / 128, T_SEQ / 128), 256, GEMM_SMEM>>>(
        n1, wq, nullptr, qkvh, T_SEQ, QKV_N, C_EMB, nullptr, nullptr);
    // scaling = relu(n1 @ scale_w^T + b) (fp32)
    hgemm<1, 0><<<dim3(C_EMB / 128, T_SEQ / 128), 256, GEMM_SMEM>>>(
        n1, ws, scaling, nullptr, T_SEQ, C_EMB, C_EMB, nullptr, scale_b);
    // per-head score scale
    scale_mean_kernel<<<(T_SEQ * N_HEAD_) / 8, 256>>>(scaling, scale_t);
    // rope + prescale (sf*scale_t*log2e) + fp16 Q/K/V planes
    qkv_prep<<<dim3(T_SEQ, 8), 128>>>(qkvh, cosb, sinb, scale_t, qh, kh, vh);
    // flash attention -> y fp16
    flash_mma<<<dim3(T_SEQ / 128, N_HEAD_), 256, FLASH_SMEM>>>(qh, kh, vh, y);
    // resid = x + y @ proj_w^T (fp32)
    hgemm<2, 0><<<dim3(C_EMB / 128, T_SEQ / 128), 256, GEMM_SMEM>>>(
        y, wp, resid, nullptr, T_SEQ, C_EMB, C_EMB, x, nullptr);
    // n2 = rmsnorm(resid) -> fp16
    rmsnorm_h<<<T_SEQ, 256>>>(resid, norm2_w, n2);
    // gate = n2 @ gate_w^T (fp32)
    hgemm<0, 0><<<dim3(FFN_N / 128, T_SEQ / 128), 256, GEMM_SMEM>>>(
        n2, wg, gate, nullptr, T_SEQ, FFN_N, C_EMB, nullptr, nullptr);
    // hbuf = silu(gate) * (n2 @ up_w^T) -> fp16
    hgemm<3, 1><<<dim3(FFN_N / 128, T_SEQ / 128), 256, GEMM_SMEM>>>(
        n2, wu, nullptr, hb, T_SEQ, FFN_N, C_EMB, gate, nullptr);
    // out = resid + hbuf @ down_w^T (fp32)
    hgemm<2, 0><<<dim3(C_EMB / 128, T_SEQ / 128), 256, GEMM_SMEM>>>(
        hb, wd, out, nullptr, T_SEQ, C_EMB, FFN_N, resid, nullptr);
}

// round 12
// speedup vs baseline: 1.5613x; 1.0265x over previous
#include <cuda_runtime.h>
#include <cuda_fp16.h>
#include <cstdint>
#include <math.h>

#define T_SEQ   2048
#define C_EMB   4096
#define QKV_N   6144
#define FFN_N   11008
#define N_HEAD_ 32

// ---------------- scratch (static device globals; allocation-free) ----------------
__device__ float g_scaling[T_SEQ * C_EMB];
__device__ float g_scale_t[N_HEAD_ * T_SEQ];
__device__ float g_resid[T_SEQ * C_EMB];
__device__ float g_gate[T_SEQ * FFN_N];

// fp16 operand planes
__device__ __half g_wq[QKV_N * C_EMB];
__device__ __half g_ws[C_EMB * C_EMB];
__device__ __half g_wp[C_EMB * C_EMB];
__device__ __half g_wg[FFN_N * C_EMB];
__device__ __half g_wu[FFN_N * C_EMB];
__device__ __half g_wd[C_EMB * FFN_N];
__device__ __half g_qkvh[T_SEQ * QKV_N];
__device__ __half g_n1[T_SEQ * C_EMB];
__device__ __half g_n2[T_SEQ * C_EMB];
__device__ __half g_y[T_SEQ * C_EMB];
__device__ __half g_hb[T_SEQ * FFN_N];
// fp16 attention operands (roped / scaled)
__device__ __half g_qh[N_HEAD_ * T_SEQ * 128];
__device__ __half g_kh[8 * T_SEQ * 128];
__device__ __half g_vh[8 * T_SEQ * 128];

// ---------------- small helpers ----------------
__device__ __forceinline__ uint32_t smem_u32(const void* p) {
    return (uint32_t)__cvta_generic_to_shared(p);
}
__device__ __forceinline__ uint32_t pack_h2(__half a, __half b) {
    __half2 p; p.x = a; p.y = b;
    return *(uint32_t*)&p;
}
__device__ __forceinline__ uint32_t pack_f2h(float a, float b) {
    return pack_h2(__float2half_rn(a), __float2half_rn(b));
}
__device__ __forceinline__ void cp_async16(void* smem_ptr, const void* gptr) {
    unsigned s = (unsigned)__cvta_generic_to_shared(smem_ptr);
    asm volatile("cp.async.cg.shared.global [%0], [%1], 16;" :: "r"(s), "l"(gptr));
}
#define CP_COMMIT() asm volatile("cp.async.commit_group;" ::: "memory")

#define LDSM4(r0, r1, r2, r3, addr) \
    asm volatile("ldmatrix.sync.aligned.m8n8.x4.shared.b16 {%0,%1,%2,%3}, [%4];" \
        : "=r"(r0), "=r"(r1), "=r"(r2), "=r"(r3) : "r"(addr))
#define LDSM4T(r0, r1, r2, r3, addr) \
    asm volatile("ldmatrix.sync.aligned.m8n8.x4.trans.shared.b16 {%0,%1,%2,%3}, [%4];" \
        : "=r"(r0), "=r"(r1), "=r"(r2), "=r"(r3) : "r"(addr))

__device__ __forceinline__ void mma_fp16(float* d, const uint32_t* a, uint32_t b0, uint32_t b1) {
    asm volatile(
        "mma.sync.aligned.m16n8k16.row.col.f32.f16.f16.f32 "
        "{%0,%1,%2,%3},{%4,%5,%6,%7},{%8,%9},{%0,%1,%2,%3};"
        : "+f"(d[0]), "+f"(d[1]), "+f"(d[2]), "+f"(d[3])
        : "r"(a[0]), "r"(a[1]), "r"(a[2]), "r"(a[3]), "r"(b0), "r"(b1));
}

// ---------------- fp32 -> fp16 convert kernel ----------------
__global__ __launch_bounds__(256) void cvt_kernel(const float* __restrict__ in,
                                                  __half* __restrict__ outp) {
    const long i = ((long)blockIdx.x * 256 + threadIdx.x) * 4;
    const float4 v = *(const float4*)(in + i);
    uint2 o = {pack_f2h(v.x, v.y), pack_f2h(v.z, v.w)};
    *(uint2*)(outp + i) = o;
}

// ---------------- RMSNorm (fp32 in -> fp16 out) ----------------
__global__ __launch_bounds__(256) void rmsnorm_h(const float* __restrict__ x,
                                                 const float* __restrict__ w,
                                                 __half* __restrict__ o) {
    const long row = blockIdx.x;
    const float* xr = x + row * C_EMB;
    const int tid = threadIdx.x;

    float4 v[4];
    float ss = 0.f;
#pragma unroll
    for (int i = 0; i < 4; i++) {
        v[i] = *(const float4*)(xr + tid * 4 + i * 1024);
        ss += v[i].x * v[i].x + v[i].y * v[i].y + v[i].z * v[i].z + v[i].w * v[i].w;
    }
#pragma unroll
    for (int off = 16; off; off >>= 1) ss += __shfl_xor_sync(0xffffffffu, ss, off);
    __shared__ float red[8];
    if ((tid & 31) == 0) red[tid >> 5] = ss;
    __syncthreads();
    float tot = red[0] + red[1] + red[2] + red[3] + red[4] + red[5] + red[6] + red[7];
    const float inv = rsqrtf(tot * (1.f / 4096.f) + 1e-5f);
#pragma unroll
    for (int i = 0; i < 4; i++) {
        float4 wv = *(const float4*)(w + tid * 4 + i * 1024);
        const long off = row * C_EMB + tid * 4 + i * 1024;
        uint2 ou = {pack_f2h(v[i].x * inv * wv.x, v[i].y * inv * wv.y),
                    pack_f2h(v[i].z * inv * wv.z, v[i].w * inv * wv.w)};
        *(uint2*)(o + off) = ou;
    }
}

// ---------------- fp16 mma GEMM: C[M,N] = A[M,K] * W[N,K]^T ----------------
#define STAGE_BYTES 32768
#define GEMM_SMEM (3 * STAGE_BYTES)

__device__ __forceinline__ void stage_tiles(char* sm, int stg,
        const __half* __restrict__ A, const __half* __restrict__ B,
        long bm, long bn, long K, int k0, int tid) {
    const int row = tid >> 1;
    const int cb = (tid & 1) * 4;
    char* st = sm + stg * STAGE_BYTES;
    const char* srcA = (const char*)(A + (bm + row) * K + k0);
    const char* srcB = (const char*)(B + (bn + row) * K + k0);
#pragma unroll
    for (int c = 0; c < 4; c++) {
        const int chunk = cb + c;
        const int sw = row * 128 + ((chunk ^ (row & 7)) << 4);
        cp_async16(st + sw, srcA + chunk * 16);
        cp_async16(st + 16384 + sw, srcB + chunk * 16);
    }
}

template <int EPI, int OUT>
__global__ __launch_bounds__(256, 2)
void hgemm(const __half* __restrict__ A, const __half* __restrict__ B,
           float* __restrict__ C, __half* __restrict__ Chalf,
           int M, int N, int K,
           const float* __restrict__ extra, const float* __restrict__ bias) {
    extern __shared__ __align__(1024) char sm[];
    const uint32_t sbase = smem_u32(sm);

    const int tid  = threadIdx.x;
    const int warp = tid >> 5;
    const int lane = tid & 31;
    const long bm = (long)blockIdx.y * 128;
    const long bn = (long)blockIdx.x * 128;
    const int wm = (warp & 1) * 64;
    const int wn = (warp >> 1) * 32;

    const int ar = (lane & 7) + ((lane >> 3) & 1) * 8;
    const int ac = lane >> 4;
    const int br = (lane & 7) + ((lane >> 4) & 1) * 8;
    const int bc = (lane >> 3) & 1;
    const int xr = lane & 7;

    float acc[4][4][4];
#pragma unroll
    for (int mt = 0; mt < 4; mt++)
#pragma unroll
        for (int nt = 0; nt < 4; nt++)
#pragma unroll
            for (int u = 0; u < 4; u++) acc[mt][nt][u] = 0.f;

    const int steps = K >> 6;
    stage_tiles(sm, 0, A, B, bm, bn, K, 0, tid);  CP_COMMIT();
    stage_tiles(sm, 1, A, B, bm, bn, K, 64, tid); CP_COMMIT();

    for (int s = 0; s < steps; ++s) {
        const int buf = s % 3;
        if (s + 1 < steps) { asm volatile("cp.async.wait_group 1;" ::: "memory"); }
        else               { asm volatile("cp.async.wait_group 0;" ::: "memory"); }
        __syncthreads();
        if (s + 2 < steps) {
            stage_tiles(sm, (s + 2) % 3, A, B, bm, bn, K, (s + 2) * 64, tid);
            CP_COMMIT();
        }
        const uint32_t st = sbase + buf * STAGE_BYTES;
        const uint32_t baseA = st + (wm + ar) * 128;
        const uint32_t baseB = st + 16384 + (wn + br) * 128;

#pragma unroll
        for (int kc = 0; kc < 4; ++kc) {
            const uint32_t aoff = ((((kc << 1) + ac) ^ xr) << 4);
            const uint32_t boff = ((((kc << 1) + bc) ^ xr) << 4);
            uint32_t Af[4][4];
#pragma unroll
            for (int mt = 0; mt < 4; ++mt)
                LDSM4(Af[mt][0], Af[mt][1], Af[mt][2], Af[mt][3], baseA + mt * 2048 + aoff);
            uint32_t Bf[2][4];
#pragma unroll
            for (int hf = 0; hf < 2; ++hf)
                LDSM4(Bf[hf][0], Bf[hf][1], Bf[hf][2], Bf[hf][3], baseB + hf * 2048 + boff);
#pragma unroll
            for (int mt = 0; mt < 4; ++mt)
#pragma unroll
                for (int nt = 0; nt < 4; ++nt) {
                    const int hf = nt >> 1, od = nt & 1;
                    mma_fp16(acc[mt][nt], Af[mt], Bf[hf][od * 2], Bf[hf][od * 2 + 1]);
                }
        }
        __syncthreads();
    }

    const int gi = lane >> 2;
    const int ci = lane & 3;
#pragma unroll
    for (int mt = 0; mt < 4; ++mt) {
        const long row  = bm + wm + mt * 16 + gi;
        const long row2 = row + 8;
#pragma unroll
        for (int nt = 0; nt < 4; ++nt) {
            const long col = bn + wn + nt * 8 + ci * 2;
            float v[4] = {acc[mt][nt][0], acc[mt][nt][1], acc[mt][nt][2], acc[mt][nt][3]};
            if (EPI == 1) {
                const float b0 = bias[col], b1 = bias[col + 1];
                v[0] = fmaxf(v[0] + b0, 0.f); v[1] = fmaxf(v[1] + b1, 0.f);
                v[2] = fmaxf(v[2] + b0, 0.f); v[3] = fmaxf(v[3] + b1, 0.f);
            } else if (EPI == 2) {
                const float2 e0 = *(const float2*)(extra + row * N + col);
                const float2 e1 = *(const float2*)(extra + row2 * N + col);
                v[0] += e0.x; v[1] += e0.y; v[2] += e1.x; v[3] += e1.y;
            } else if (EPI == 3) {
                const float2 g0 = *(const float2*)(extra + row * N + col);
                const float2 g1 = *(const float2*)(extra + row2 * N + col);
                v[0] *= g0.x / (1.f + __expf(-g0.x));
                v[1] *= g0.y / (1.f + __expf(-g0.y));
                v[2] *= g1.x / (1.f + __expf(-g1.x));
                v[3] *= g1.y / (1.f + __expf(-g1.y));
            }
            if (OUT == 0) {
                float2 o0 = {v[0], v[1]}, o1 = {v[2], v[3]};
                *(float2*)(C + row * N + col)  = o0;
                *(float2*)(C + row2 * N + col) = o1;
            } else {
                *(uint32_t*)(Chalf + row * N + col)  = pack_f2h(v[0], v[1]);
                *(uint32_t*)(Chalf + row2 * N + col) = pack_f2h(v[2], v[3]);
            }
        }
    }
}

// ---------------- scale_t[h][t] = mean_d scaling[t][h*128+d] ----------------
__global__ __launch_bounds__(256) void scale_mean_kernel(const float* __restrict__ scaling,
                                                         float* __restrict__ scale_t) {
    const int wid = (blockIdx.x * 256 + threadIdx.x) >> 5;
    const int lane = threadIdx.x & 31;
    const int t = wid >> 5;
    const int h = wid & 31;
    const float4 v = *(const float4*)(scaling + (long)t * C_EMB + h * 128 + lane * 4);
    float s = v.x + v.y + v.z + v.w;
#pragma unroll
    for (int o = 16; o; o >>= 1) s += __shfl_xor_sync(0xffffffffu, s, o);
    if (lane == 0) scale_t[h * T_SEQ + t] = s * (1.f / 128.f);
}

// ---------------- qkv_prep: rope + q prescale (incl. log2e) + fp16 Q/K/V planes ----------------
__global__ __launch_bounds__(128) void qkv_prep(const __half* __restrict__ qkv,
                                                const float* __restrict__ cosb,
                                                const float* __restrict__ sinb,
                                                const float* __restrict__ scale_t,
                                                __half* __restrict__ qh,
                                                __half* __restrict__ kh,
                                                __half* __restrict__ vh) {
    const int t = blockIdx.x;
    const int g = blockIdx.y;
    const int d = threadIdx.x;
    const float c = cosb[t * 128 + d];
    const float s = sinb[t * 128 + d];
    const float sfl = 0.08838834764831845f * 1.4426950408889634f;  // sf * log2(e)
    const __half* base = qkv + (long)t * QKV_N + g * 768;

#pragma unroll
    for (int slot = 0; slot < 4; ++slot) {
        const __half* p = base + slot * 128;
        const float xd = __half2float(p[d]);
        const float xo = __half2float(p[d ^ 64]);
        const float rot = (d < 64) ? -xo : xo;
        const int h = g * 4 + slot;
        const float q = (xd * c + rot * s) * sfl * scale_t[h * T_SEQ + t];
        qh[((long)h * T_SEQ + t) * 128 + d] = __float2half_rn(q);
    }
    {
        const __half* p = base + 4 * 128;
        const float xd = __half2float(p[d]);
        const float xo = __half2float(p[d ^ 64]);
        const float rot = (d < 64) ? -xo : xo;
        kh[((long)g * T_SEQ + t) * 128 + d] = __float2half_rn(xd * c + rot * s);
    }
    vh[((long)g * T_SEQ + t) * 128 + d] = base[5 * 128 + d];
}

// ---------------- flash attention on fp16 mma (FA2-style, non-causal, exp2 softmax) ----------------
#define FL_QS     0
#define FL_STAGE0 32768
#define FL_STAGEB 32768
#define FLASH_SMEM (32768 + 2 * 32768)

__global__ __launch_bounds__(256, 1)
void flash_mma(const __half* __restrict__ qh, const __half* __restrict__ kh,
               const __half* __restrict__ vh, __half* __restrict__ y) {
    extern __shared__ __align__(1024) char sm[];
    const uint32_t sbase = smem_u32(sm);

    const int tid  = threadIdx.x;
    const int warp = tid >> 5;
    const int lane = tid & 31;
    const int qb = blockIdx.x;
    const int h  = blockIdx.y;
    const int g  = h >> 2;

    // --- load Q tile (128 rows x 128 halves), swizzled ---
    {
        const int row = tid >> 1;
        const int cb = (tid & 1) * 8;
        const char* src = (const char*)(qh + ((long)h * T_SEQ + qb * 128 + row) * 128);
#pragma unroll
        for (int c = 0; c < 8; ++c) {
            const int chunk = cb + c;
            const int sw = row * 256 + ((chunk ^ (row & 7)) << 4);
            cp_async16(sm + FL_QS + sw, src + chunk * 16);
        }
        CP_COMMIT();
    }
    // --- stage 0 K/V ---
    {
        const int row = tid >> 2;
        const int cb = (tid & 3) * 4;
        const char* srcK = (const char*)(kh + ((long)g * T_SEQ + row) * 128);
        const char* srcV = (const char*)(vh + ((long)g * T_SEQ + row) * 128);
#pragma unroll
        for (int c = 0; c < 4; ++c) {
            const int chunk = cb + c;
            const int sw = row * 256 + ((chunk ^ (row & 7)) << 4);
            cp_async16(sm + FL_STAGE0 + sw, srcK + chunk * 16);
            cp_async16(sm + FL_STAGE0 + 16384 + sw, srcV + chunk * 16);
        }
        CP_COMMIT();
    }

    asm volatile("cp.async.wait_group 1;" ::: "memory");
    __syncthreads();

    const int ar = (lane & 7) + ((lane >> 3) & 1) * 8;
    const int ac = lane >> 4;
    uint32_t Qf[8][4];
#pragma unroll
    for (int kb = 0; kb < 8; ++kb) {
        const int qrow = warp * 16 + ar;
        const uint32_t addr = sbase + FL_QS + qrow * 256 + ((((kb << 1) + ac) ^ (qrow & 7)) << 4);
        LDSM4(Qf[kb][0], Qf[kb][1], Qf[kb][2], Qf[kb][3], addr);
    }

    const int br = (lane & 7) + ((lane >> 4) & 1) * 8;
    const int bc = (lane >> 3) & 1;
    const int vr = (lane & 7) + ((lane >> 3) & 1) * 8;
    const int vc = lane >> 4;

    float acc[16][4];
#pragma unroll
    for (int dn = 0; dn < 16; ++dn)
#pragma unroll
        for (int u = 0; u < 4; ++u) acc[dn][u] = 0.f;
    float mrow[2] = {-1e30f, -1e30f};
    float lrow[2] = {0.f, 0.f};

    for (int kt = 0; kt < 32; ++kt) {
        asm volatile("cp.async.wait_group 0;" ::: "memory");
        __syncthreads();
        if (kt + 1 < 32) {
            const int row = tid >> 2;
            const int cb = (tid & 3) * 4;
            char* st = sm + FL_STAGE0 + ((kt + 1) & 1) * FL_STAGEB;
            const char* srcK = (const char*)(kh + ((long)g * T_SEQ + (kt + 1) * 64 + row) * 128);
            const char* srcV = (const char*)(vh + ((long)g * T_SEQ + (kt + 1) * 64 + row) * 128);
#pragma unroll
            for (int c = 0; c < 4; ++c) {
                const int chunk = cb + c;
                const int sw = row * 256 + ((chunk ^ (row & 7)) << 4);
                cp_async16(st + sw, srcK + chunk * 16);
                cp_async16(st + 16384 + sw, srcV + chunk * 16);
            }
            CP_COMMIT();
        }
        const uint32_t Ks = sbase + FL_STAGE0 + (kt & 1) * FL_STAGEB;
        const uint32_t Vs = Ks + 16384;

        float sacc[8][4];
#pragma unroll
        for (int j = 0; j < 8; ++j)
#pragma unroll
            for (int u = 0; u < 4; ++u) sacc[j][u] = 0.f;
#pragma unroll
        for (int kb = 0; kb < 8; ++kb) {
            uint32_t Bf[4][4];
#pragma unroll
            for (int n16 = 0; n16 < 4; ++n16) {
                const int krow = n16 * 16 + br;
                const uint32_t addr = Ks + krow * 256 + ((((kb << 1) + bc) ^ (krow & 7)) << 4);
                LDSM4(Bf[n16][0], Bf[n16][1], Bf[n16][2], Bf[n16][3], addr);
            }
#pragma unroll
            for (int nt = 0; nt < 8; ++nt)
                mma_fp16(sacc[nt], Qf[kb], Bf[nt >> 1][(nt & 1) * 2], Bf[nt >> 1][(nt & 1) * 2 + 1]);
        }

        // online softmax in exp2 domain (log2e folded into Q prescale)
#pragma unroll
        for (int rh = 0; rh < 2; ++rh) {
            float tmax = -1e30f;
#pragma unroll
            for (int j = 0; j < 8; ++j)
                tmax = fmaxf(tmax, fmaxf(sacc[j][rh * 2], sacc[j][rh * 2 + 1]));
            tmax = fmaxf(tmax, __shfl_xor_sync(0xffffffffu, tmax, 1));
            tmax = fmaxf(tmax, __shfl_xor_sync(0xffffffffu, tmax, 2));
            const float mnew = fmaxf(mrow[rh], tmax);
            const float corr = exp2f(mrow[rh] - mnew);
            float psum = 0.f;
#pragma unroll
            for (int j = 0; j < 8; ++j) {
                const float p0 = exp2f(sacc[j][rh * 2] - mnew);
                const float p1 = exp2f(sacc[j][rh * 2 + 1] - mnew);
                sacc[j][rh * 2] = p0;
                sacc[j][rh * 2 + 1] = p1;
                psum += p0 + p1;
            }
            psum += __shfl_xor_sync(0xffffffffu, psum, 1);
            psum += __shfl_xor_sync(0xffffffffu, psum, 2);
            lrow[rh] = lrow[rh] * corr + psum;
            mrow[rh] = mnew;
#pragma unroll
            for (int dn = 0; dn < 16; ++dn) {
                acc[dn][rh * 2] *= corr;
                acc[dn][rh * 2 + 1] *= corr;
            }
        }

        uint32_t Pa[4][4];
#pragma unroll
        for (int t = 0; t < 4; ++t) {
            Pa[t][0] = pack_f2h(sacc[2 * t][0], sacc[2 * t][1]);
            Pa[t][1] = pack_f2h(sacc[2 * t][2], sacc[2 * t][3]);
            Pa[t][2] = pack_f2h(sacc[2 * t + 1][0], sacc[2 * t + 1][1]);
            Pa[t][3] = pack_f2h(sacc[2 * t + 1][2], sacc[2 * t + 1][3]);
        }

#pragma unroll
        for (int t = 0; t < 4; ++t) {
            const int vrow = t * 16 + vr;
#pragma unroll
            for (int dn16 = 0; dn16 < 8; ++dn16) {
                uint32_t Vt[4];
                const uint32_t addr = Vs + vrow * 256 + ((((dn16 << 1) + vc) ^ (vrow & 7)) << 4);
                LDSM4T(Vt[0], Vt[1], Vt[2], Vt[3], addr);
                mma_fp16(acc[dn16 * 2],     Pa[t], Vt[0], Vt[1]);
                mma_fp16(acc[dn16 * 2 + 1], Pa[t], Vt[2], Vt[3]);
            }
        }
    }

    const int gi = lane >> 2;
    const int ci = lane & 3;
    const float il0 = 1.f / lrow[0];
    const float il1 = 1.f / lrow[1];
    const long row0 = (long)qb * 128 + warp * 16 + gi;
    const long row1 = row0 + 8;
#pragma unroll
    for (int dn = 0; dn < 16; ++dn) {
        const long col = h * 128 + dn * 8 + ci * 2;
        *(uint32_t*)(y + row0 * C_EMB + col) = pack_f2h(acc[dn][0] * il0, acc[dn][1] * il0);
        *(uint32_t*)(y + row1 * C_EMB + col) = pack_f2h(acc[dn][2] * il1, acc[dn][3] * il1);
    }
}

// ---------------- host launcher ----------------
extern "C" void kernel_launch(void* const* d_in, const int* in_sizes, int n_in,
                              void* d_out, int out_size) {
    const float* x       = (const float*)d_in[0];
    const float* cosb    = (const float*)d_in[1];
    const float* sinb    = (const float*)d_in[2];
    const float* norm1_w = (const float*)d_in[3];
    const float* norm2_w = (const float*)d_in[4];
    const float* attn_w  = (const float*)d_in[5];
    const float* proj_w  = (const float*)d_in[6];
    const float* scale_w = (const float*)d_in[7];
    const float* scale_b = (const float*)d_in[8];
    const float* gate_w  = (const float*)d_in[9];
    const float* up_w    = (const float*)d_in[10];
    const float* down_w  = (const float*)d_in[11];
    float* out = (float*)d_out;

    float *scaling, *scale_t, *resid, *gate;
    cudaGetSymbolAddress((void**)&scaling, g_scaling);
    cudaGetSymbolAddress((void**)&scale_t, g_scale_t);
    cudaGetSymbolAddress((void**)&resid, g_resid);
    cudaGetSymbolAddress((void**)&gate, g_gate);

    __half *wq, *ws, *wp, *wg, *wu, *wd, *qkvh, *n1, *n2, *y, *hb, *qh, *kh, *vh;
    cudaGetSymbolAddress((void**)&wq, g_wq);
    cudaGetSymbolAddress((void**)&ws, g_ws);
    cudaGetSymbolAddress((void**)&wp, g_wp);
    cudaGetSymbolAddress((void**)&wg, g_wg);
    cudaGetSymbolAddress((void**)&wu, g_wu);
    cudaGetSymbolAddress((void**)&wd, g_wd);
    cudaGetSymbolAddress((void**)&qkvh, g_qkvh);
    cudaGetSymbolAddress((void**)&n1, g_n1);
    cudaGetSymbolAddress((void**)&n2, g_n2);
    cudaGetSymbolAddress((void**)&y, g_y);
    cudaGetSymbolAddress((void**)&hb, g_hb);
    cudaGetSymbolAddress((void**)&qh, g_qh);
    cudaGetSymbolAddress((void**)&kh, g_kh);
    cudaGetSymbolAddress((void**)&vh, g_vh);

    cudaFuncSetAttribute(flash_mma, cudaFuncAttributeMaxDynamicSharedMemorySize, FLASH_SMEM);
    cudaFuncSetAttribute(hgemm<0, 0>, cudaFuncAttributeMaxDynamicSharedMemorySize, GEMM_SMEM);
    cudaFuncSetAttribute(hgemm<0, 1>, cudaFuncAttributeMaxDynamicSharedMemorySize, GEMM_SMEM);
    cudaFuncSetAttribute(hgemm<1, 0>, cudaFuncAttributeMaxDynamicSharedMemorySize, GEMM_SMEM);
    cudaFuncSetAttribute(hgemm<2, 0>, cudaFuncAttributeMaxDynamicSharedMemorySize, GEMM_SMEM);
    cudaFuncSetAttribute(hgemm<3, 1>, cudaFuncAttributeMaxDynamicSharedMemorySize, GEMM_SMEM);

    // lazily-created side stream + events for convert/compute overlap
    static cudaStream_t s_cvt = nullptr;
    static cudaEvent_t evFork = nullptr, evWq = nullptr, evWs = nullptr,
                       evWp = nullptr, evWg = nullptr, evWu = nullptr, evWd = nullptr;
    if (s_cvt == nullptr) {
        cudaStreamCreateWithFlags(&s_cvt, cudaStreamNonBlocking);
        cudaEventCreateWithFlags(&evFork, cudaEventDisableTiming);
        cudaEventCreateWithFlags(&evWq, cudaEventDisableTiming);
        cudaEventCreateWithFlags(&evWs, cudaEventDisableTiming);
        cudaEventCreateWithFlags(&evWp, cudaEventDisableTiming);
        cudaEventCreateWithFlags(&evWg, cudaEventDisableTiming);
        cudaEventCreateWithFlags(&evWu, cudaEventDisableTiming);
        cudaEventCreateWithFlags(&evWd, cudaEventDisableTiming);
    }

    // fork: side stream carries all weight converts, DRAM-bound, overlapped
    // with the tensor-bound main chain.
    cudaEventRecord(evFork, 0);
    cudaStreamWaitEvent(s_cvt, evFork, 0);
    cvt_kernel<<<(QKV_N * C_EMB) / 1024, 256, 0, s_cvt>>>(attn_w, wq);
    cudaEventRecord(evWq, s_cvt);
    cvt_kernel<<<(C_EMB * C_EMB) / 1024, 256, 0, s_cvt>>>(scale_w, ws);
    cudaEventRecord(evWs, s_cvt);
    cvt_kernel<<<(C_EMB * C_EMB) / 1024, 256, 0, s_cvt>>>(proj_w, wp);
    cudaEventRecord(evWp, s_cvt);
    cvt_kernel<<<(FFN_N * C_EMB) / 1024, 256, 0, s_cvt>>>(gate_w, wg);
    cudaEventRecord(evWg, s_cvt);
    cvt_kernel<<<(FFN_N * C_EMB) / 1024, 256, 0, s_cvt>>>(up_w, wu);
    cudaEventRecord(evWu, s_cvt);
    cvt_kernel<<<(C_EMB * FFN_N) / 1024, 256, 0, s_cvt>>>(down_w, wd);
    cudaEventRecord(evWd, s_cvt);

    // main chain (legacy default stream, captured by the harness)
    // n1 = rmsnorm(x, norm1_w) -> fp16   (overlaps with wq convert)
    rmsnorm_h<<<T_SEQ, 256>>>(x, norm1_w, n1);
    // qkv = n1 @ attn_w^T -> fp16
    cudaStreamWaitEvent(0, evWq, 0);
    hgemm<0, 1><<<dim3(QKV_N / 128, T_SEQ / 128), 256, GEMM_SMEM>>>(
        n1, wq, nullptr, qkvh, T_SEQ, QKV_N, C_EMB, nullptr, nullptr);
    // scaling = relu(n1 @ scale_w^T + b) (fp32)
    cudaStreamWaitEvent(0, evWs, 0);
    hgemm<1, 0><<<dim3(C_EMB / 128, T_SEQ / 128), 256, GEMM_SMEM>>>(
        n1, ws, scaling, nullptr, T_SEQ, C_EMB, C_EMB, nullptr, scale_b);
    // per-head score scale
    scale_mean_kernel<<<(T_SEQ * N_HEAD_) / 8, 256>>>(scaling, scale_t);
    // rope + prescale (sf*scale_t*log2e) + fp16 Q/K/V planes
    qkv_prep<<<dim3(T_SEQ, 8), 128>>>(qkvh, cosb, sinb, scale_t, qh, kh, vh);
    // flash attention -> y fp16
    flash_mma<<<dim3(T_SEQ / 128, N_HEAD_), 256, FLASH_SMEM>>>(qh, kh, vh, y);
    // resid = x + y @ proj_w^T (fp32)
    cudaStreamWaitEvent(0, evWp, 0);
    hgemm<2, 0><<<dim3(C_EMB / 128, T_SEQ / 128), 256, GEMM_SMEM>>>(
        y, wp, resid, nullptr, T_SEQ, C_EMB, C_EMB, x, nullptr);
    // n2 = rmsnorm(resid) -> fp16
    rmsnorm_h<<<T_SEQ, 256>>>(resid, norm2_w, n2);
    // gate = n2 @ gate_w^T (fp32)
    cudaStreamWaitEvent(0, evWg, 0);
    hgemm<0, 0><<<dim3(FFN_N / 128, T_SEQ / 128), 256, GEMM_SMEM>>>(
        n2, wg, gate, nullptr, T_SEQ, FFN_N, C_EMB, nullptr, nullptr);
    // hbuf = silu(gate) * (n2 @ up_w^T) -> fp16
    cudaStreamWaitEvent(0, evWu, 0);
    hgemm<3, 1><<<dim3(FFN_N / 128, T_SEQ / 128), 256, GEMM_SMEM>>>(
        n2, wu, nullptr, hb, T_SEQ, FFN_N, C_EMB, gate, nullptr);
    // out = resid + hbuf @ down_w^T (fp32)  (joins side stream via evWd)
    cudaStreamWaitEvent(0, evWd, 0);
    hgemm<2, 0><<<dim3(C_EMB / 128, T_SEQ / 128), 256, GEMM_SMEM>>>(
        hb, wd, out, nullptr, T_SEQ, C_EMB, FFN_N, resid, nullptr);
}

// round 15
// speedup vs baseline: 1.5913x; 1.0193x over previous
#include <cuda_runtime.h>
#include <cuda_fp16.h>
#include <cstdint>
#include <math.h>

#define T_SEQ   2048
#define C_EMB   4096
#define QKV_N   6144
#define FFN_N   11008
#define N_HEAD_ 32

// ---------------- scratch (static device globals; allocation-free) ----------------
__device__ float g_scale_t[N_HEAD_ * T_SEQ];
__device__ float g_resid[T_SEQ * C_EMB];
__device__ float g_gate[T_SEQ * FFN_N];

// fp16 operand planes
__device__ __half g_wq[QKV_N * C_EMB];
__device__ __half g_ws[C_EMB * C_EMB];
__device__ __half g_wp[C_EMB * C_EMB];
__device__ __half g_wg[FFN_N * C_EMB];
__device__ __half g_wu[FFN_N * C_EMB];
__device__ __half g_wd[C_EMB * FFN_N];
__device__ __half g_qkvh[T_SEQ * QKV_N];
__device__ __half g_n1[T_SEQ * C_EMB];
__device__ __half g_n2[T_SEQ * C_EMB];
__device__ __half g_y[T_SEQ * C_EMB];
__device__ __half g_hb[T_SEQ * FFN_N];
// fp16 attention operands (roped / scaled)
__device__ __half g_qh[N_HEAD_ * T_SEQ * 128];
__device__ __half g_kh[8 * T_SEQ * 128];
__device__ __half g_vh[8 * T_SEQ * 128];

// ---------------- small helpers ----------------
__device__ __forceinline__ uint32_t smem_u32(const void* p) {
    return (uint32_t)__cvta_generic_to_shared(p);
}
__device__ __forceinline__ uint32_t pack_h2(__half a, __half b) {
    __half2 p; p.x = a; p.y = b;
    return *(uint32_t*)&p;
}
__device__ __forceinline__ uint32_t pack_f2h(float a, float b) {
    return pack_h2(__float2half_rn(a), __float2half_rn(b));
}
__device__ __forceinline__ void cp_async16(void* smem_ptr, const void* gptr) {
    unsigned s = (unsigned)__cvta_generic_to_shared(smem_ptr);
    asm volatile("cp.async.cg.shared.global [%0], [%1], 16;" :: "r"(s), "l"(gptr));
}
#define CP_COMMIT() asm volatile("cp.async.commit_group;" ::: "memory")

#define LDSM4(r0, r1, r2, r3, addr) \
    asm volatile("ldmatrix.sync.aligned.m8n8.x4.shared.b16 {%0,%1,%2,%3}, [%4];" \
        : "=r"(r0), "=r"(r1), "=r"(r2), "=r"(r3) : "r"(addr))
#define LDSM4T(r0, r1, r2, r3, addr) \
    asm volatile("ldmatrix.sync.aligned.m8n8.x4.trans.shared.b16 {%0,%1,%2,%3}, [%4];" \
        : "=r"(r0), "=r"(r1), "=r"(r2), "=r"(r3) : "r"(addr))

__device__ __forceinline__ void mma_fp16(float* d, const uint32_t* a, uint32_t b0, uint32_t b1) {
    asm volatile(
        "mma.sync.aligned.m16n8k16.row.col.f32.f16.f16.f32 "
        "{%0,%1,%2,%3},{%4,%5,%6,%7},{%8,%9},{%0,%1,%2,%3};"
        : "+f"(d[0]), "+f"(d[1]), "+f"(d[2]), "+f"(d[3])
        : "r"(a[0]), "r"(a[1]), "r"(a[2]), "r"(a[3]), "r"(b0), "r"(b1));
}

// ---------------- fp32 -> fp16 convert kernel ----------------
__global__ __launch_bounds__(256) void cvt_kernel(const float* __restrict__ in,
                                                  __half* __restrict__ outp) {
    const long i = ((long)blockIdx.x * 256 + threadIdx.x) * 4;
    const float4 v = *(const float4*)(in + i);
    uint2 o = {pack_f2h(v.x, v.y), pack_f2h(v.z, v.w)};
    *(uint2*)(outp + i) = o;
}

// ---------------- RMSNorm (fp32 in -> fp16 out) ----------------
__global__ __launch_bounds__(256) void rmsnorm_h(const float* __restrict__ x,
                                                 const float* __restrict__ w,
                                                 __half* __restrict__ o) {
    const long row = blockIdx.x;
    const float* xr = x + row * C_EMB;
    const int tid = threadIdx.x;

    float4 v[4];
    float ss = 0.f;
#pragma unroll
    for (int i = 0; i < 4; i++) {
        v[i] = *(const float4*)(xr + tid * 4 + i * 1024);
        ss += v[i].x * v[i].x + v[i].y * v[i].y + v[i].z * v[i].z + v[i].w * v[i].w;
    }
#pragma unroll
    for (int off = 16; off; off >>= 1) ss += __shfl_xor_sync(0xffffffffu, ss, off);
    __shared__ float red[8];
    if ((tid & 31) == 0) red[tid >> 5] = ss;
    __syncthreads();
    float tot = red[0] + red[1] + red[2] + red[3] + red[4] + red[5] + red[6] + red[7];
    const float inv = rsqrtf(tot * (1.f / 4096.f) + 1e-5f);
#pragma unroll
    for (int i = 0; i < 4; i++) {
        float4 wv = *(const float4*)(w + tid * 4 + i * 1024);
        const long off = row * C_EMB + tid * 4 + i * 1024;
        uint2 ou = {pack_f2h(v[i].x * inv * wv.x, v[i].y * inv * wv.y),
                    pack_f2h(v[i].z * inv * wv.z, v[i].w * inv * wv.w)};
        *(uint2*)(o + off) = ou;
    }
}

// ---------------- fp16 mma GEMM: C[M,N] = A[M,K] * W[N,K]^T ----------------
// EPI: 0 none, 1 relu(+bias), 2 +extra, 3 silu(extra)*acc,
//      4 relu(+bias) reduced over the 128-col tile -> scale_t (C = scale_t, no C-matrix write)
#define STAGE_BYTES 32768
#define GEMM_SMEM (3 * STAGE_BYTES)

__device__ __forceinline__ void stage_tiles(char* sm, int stg,
        const __half* __restrict__ A, const __half* __restrict__ B,
        long bm, long bn, long K, int k0, int tid) {
    const int row = tid >> 1;
    const int cb = (tid & 1) * 4;
    char* st = sm + stg * STAGE_BYTES;
    const char* srcA = (const char*)(A + (bm + row) * K + k0);
    const char* srcB = (const char*)(B + (bn + row) * K + k0);
#pragma unroll
    for (int c = 0; c < 4; c++) {
        const int chunk = cb + c;
        const int sw = row * 128 + ((chunk ^ (row & 7)) << 4);
        cp_async16(st + sw, srcA + chunk * 16);
        cp_async16(st + 16384 + sw, srcB + chunk * 16);
    }
}

template <int EPI, int OUT>
__global__ __launch_bounds__(256, 2)
void hgemm(const __half* __restrict__ A, const __half* __restrict__ B,
           float* __restrict__ C, __half* __restrict__ Chalf,
           int M, int N, int K,
           const float* __restrict__ extra, const float* __restrict__ bias) {
    extern __shared__ __align__(1024) char sm[];
    const uint32_t sbase = smem_u32(sm);

    const int tid  = threadIdx.x;
    const int warp = tid >> 5;
    const int lane = tid & 31;
    const long bm = (long)blockIdx.y * 128;
    const long bn = (long)blockIdx.x * 128;
    const int wm = (warp & 1) * 64;
    const int wn = (warp >> 1) * 32;

    const int ar = (lane & 7) + ((lane >> 3) & 1) * 8;
    const int ac = lane >> 4;
    const int br = (lane & 7) + ((lane >> 4) & 1) * 8;
    const int bc = (lane >> 3) & 1;
    const int xr = lane & 7;

    float acc[4][4][4];
#pragma unroll
    for (int mt = 0; mt < 4; mt++)
#pragma unroll
        for (int nt = 0; nt < 4; nt++)
#pragma unroll
            for (int u = 0; u < 4; u++) acc[mt][nt][u] = 0.f;

    const int steps = K >> 6;
    stage_tiles(sm, 0, A, B, bm, bn, K, 0, tid);  CP_COMMIT();
    stage_tiles(sm, 1, A, B, bm, bn, K, 64, tid); CP_COMMIT();

    for (int s = 0; s < steps; ++s) {
        const int buf = s % 3;
        if (s + 1 < steps) { asm volatile("cp.async.wait_group 1;" ::: "memory"); }
        else               { asm volatile("cp.async.wait_group 0;" ::: "memory"); }
        __syncthreads();
        if (s + 2 < steps) {
            stage_tiles(sm, (s + 2) % 3, A, B, bm, bn, K, (s + 2) * 64, tid);
            CP_COMMIT();
        }
        const uint32_t st = sbase + buf * STAGE_BYTES;
        const uint32_t baseA = st + (wm + ar) * 128;
        const uint32_t baseB = st + 16384 + (wn + br) * 128;

#pragma unroll
        for (int kc = 0; kc < 4; ++kc) {
            const uint32_t aoff = ((((kc << 1) + ac) ^ xr) << 4);
            const uint32_t boff = ((((kc << 1) + bc) ^ xr) << 4);
            uint32_t Af[4][4];
#pragma unroll
            for (int mt = 0; mt < 4; ++mt)
                LDSM4(Af[mt][0], Af[mt][1], Af[mt][2], Af[mt][3], baseA + mt * 2048 + aoff);
            uint32_t Bf[2][4];
#pragma unroll
            for (int hf = 0; hf < 2; ++hf)
                LDSM4(Bf[hf][0], Bf[hf][1], Bf[hf][2], Bf[hf][3], baseB + hf * 2048 + boff);
#pragma unroll
            for (int mt = 0; mt < 4; ++mt)
#pragma unroll
                for (int nt = 0; nt < 4; ++nt) {
                    const int hf = nt >> 1, od = nt & 1;
                    mma_fp16(acc[mt][nt], Af[mt], Bf[hf][od * 2], Bf[hf][od * 2 + 1]);
                }
        }
        __syncthreads();
    }

    const int gi = lane >> 2;
    const int ci = lane & 3;

    if (EPI == 4) {
        // relu(acc + bias), reduce over all 128 cols of this tile -> scale_t[h][t]
        // h == blockIdx.x (tile spans one head's 128 dims), t = bm + local row.
        float rsum[8];
#pragma unroll
        for (int mt = 0; mt < 4; ++mt) {
            float s0 = 0.f, s1 = 0.f;
#pragma unroll
            for (int nt = 0; nt < 4; ++nt) {
                const long col = bn + wn + nt * 8 + ci * 2;
                const float b0 = bias[col], b1 = bias[col + 1];
                s0 += fmaxf(acc[mt][nt][0] + b0, 0.f) + fmaxf(acc[mt][nt][1] + b1, 0.f);
                s1 += fmaxf(acc[mt][nt][2] + b0, 0.f) + fmaxf(acc[mt][nt][3] + b1, 0.f);
            }
            rsum[mt * 2]     = s0;
            rsum[mt * 2 + 1] = s1;
        }
#pragma unroll
        for (int i = 0; i < 8; ++i) {
            rsum[i] += __shfl_xor_sync(0xffffffffu, rsum[i], 1);
            rsum[i] += __shfl_xor_sync(0xffffffffu, rsum[i], 2);
        }
        float* part = (float*)sm;  // [128][4]
        __syncthreads();
        if (ci == 0) {
            const int wc = warp >> 1;
#pragma unroll
            for (int mt = 0; mt < 4; ++mt) {
                part[(wm + mt * 16 + gi) * 4 + wc]     = rsum[mt * 2];
                part[(wm + mt * 16 + gi + 8) * 4 + wc] = rsum[mt * 2 + 1];
            }
        }
        __syncthreads();
        if (tid < 128) {
            const float s = part[tid * 4] + part[tid * 4 + 1] + part[tid * 4 + 2] + part[tid * 4 + 3];
            C[(long)blockIdx.x * T_SEQ + bm + tid] = s * (1.f / 128.f);
        }
        return;
    }

#pragma unroll
    for (int mt = 0; mt < 4; ++mt) {
        const long row  = bm + wm + mt * 16 + gi;
        const long row2 = row + 8;
#pragma unroll
        for (int nt = 0; nt < 4; ++nt) {
            const long col = bn + wn + nt * 8 + ci * 2;
            float v[4] = {acc[mt][nt][0], acc[mt][nt][1], acc[mt][nt][2], acc[mt][nt][3]};
            if (EPI == 1) {
                const float b0 = bias[col], b1 = bias[col + 1];
                v[0] = fmaxf(v[0] + b0, 0.f); v[1] = fmaxf(v[1] + b1, 0.f);
                v[2] = fmaxf(v[2] + b0, 0.f); v[3] = fmaxf(v[3] + b1, 0.f);
            } else if (EPI == 2) {
                const float2 e0 = *(const float2*)(extra + row * N + col);
                const float2 e1 = *(const float2*)(extra + row2 * N + col);
                v[0] += e0.x; v[1] += e0.y; v[2] += e1.x; v[3] += e1.y;
            } else if (EPI == 3) {
                const float2 g0 = *(const float2*)(extra + row * N + col);
                const float2 g1 = *(const float2*)(extra + row2 * N + col);
                v[0] *= g0.x / (1.f + __expf(-g0.x));
                v[1] *= g0.y / (1.f + __expf(-g0.y));
                v[2] *= g1.x / (1.f + __expf(-g1.x));
                v[3] *= g1.y / (1.f + __expf(-g1.y));
            }
            if (OUT == 0) {
                float2 o0 = {v[0], v[1]}, o1 = {v[2], v[3]};
                *(float2*)(C + row * N + col)  = o0;
                *(float2*)(C + row2 * N + col) = o1;
            } else {
                *(uint32_t*)(Chalf + row * N + col)  = pack_f2h(v[0], v[1]);
                *(uint32_t*)(Chalf + row2 * N + col) = pack_f2h(v[2], v[3]);
            }
        }
    }
}

// ---------------- qkv_prep: rope + q prescale (incl. log2e) + fp16 Q/K/V planes ----------------
__global__ __launch_bounds__(128) void qkv_prep(const __half* __restrict__ qkv,
                                                const float* __restrict__ cosb,
                                                const float* __restrict__ sinb,
                                                const float* __restrict__ scale_t,
                                                __half* __restrict__ qh,
                                                __half* __restrict__ kh,
                                                __half* __restrict__ vh) {
    const int t = blockIdx.x;
    const int g = blockIdx.y;
    const int d = threadIdx.x;
    const float c = cosb[t * 128 + d];
    const float s = sinb[t * 128 + d];
    const float sfl = 0.08838834764831845f * 1.4426950408889634f;  // sf * log2(e)
    const __half* base = qkv + (long)t * QKV_N + g * 768;

#pragma unroll
    for (int slot = 0; slot < 4; ++slot) {
        const __half* p = base + slot * 128;
        const float xd = __half2float(p[d]);
        const float xo = __half2float(p[d ^ 64]);
        const float rot = (d < 64) ? -xo : xo;
        const int h = g * 4 + slot;
        const float q = (xd * c + rot * s) * sfl * scale_t[h * T_SEQ + t];
        qh[((long)h * T_SEQ + t) * 128 + d] = __float2half_rn(q);
    }
    {
        const __half* p = base + 4 * 128;
        const float xd = __half2float(p[d]);
        const float xo = __half2float(p[d ^ 64]);
        const float rot = (d < 64) ? -xo : xo;
        kh[((long)g * T_SEQ + t) * 128 + d] = __float2half_rn(xd * c + rot * s);
    }
    vh[((long)g * T_SEQ + t) * 128 + d] = base[5 * 128 + d];
}

// ---------------- flash attention on fp16 mma (FA2-style, non-causal, exp2 softmax) ----------------
#define FL_QS     0
#define FL_STAGE0 32768
#define FL_STAGEB 32768
#define FLASH_SMEM (32768 + 2 * 32768)

__global__ __launch_bounds__(256, 1)
void flash_mma(const __half* __restrict__ qh, const __half* __restrict__ kh,
               const __half* __restrict__ vh, __half* __restrict__ y) {
    extern __shared__ __align__(1024) char sm[];
    const uint32_t sbase = smem_u32(sm);

    const int tid  = threadIdx.x;
    const int warp = tid >> 5;
    const int lane = tid & 31;
    const int qb = blockIdx.x;
    const int h  = blockIdx.y;
    const int g  = h >> 2;

    {
        const int row = tid >> 1;
        const int cb = (tid & 1) * 8;
        const char* src = (const char*)(qh + ((long)h * T_SEQ + qb * 128 + row) * 128);
#pragma unroll
        for (int c = 0; c < 8; ++c) {
            const int chunk = cb + c;
            const int sw = row * 256 + ((chunk ^ (row & 7)) << 4);
            cp_async16(sm + FL_QS + sw, src + chunk * 16);
        }
        CP_COMMIT();
    }
    {
        const int row = tid >> 2;
        const int cb = (tid & 3) * 4;
        const char* srcK = (const char*)(kh + ((long)g * T_SEQ + row) * 128);
        const char* srcV = (const char*)(vh + ((long)g * T_SEQ + row) * 128);
#pragma unroll
        for (int c = 0; c < 4; ++c) {
            const int chunk = cb + c;
            const int sw = row * 256 + ((chunk ^ (row & 7)) << 4);
            cp_async16(sm + FL_STAGE0 + sw, srcK + chunk * 16);
            cp_async16(sm + FL_STAGE0 + 16384 + sw, srcV + chunk * 16);
        }
        CP_COMMIT();
    }

    asm volatile("cp.async.wait_group 1;" ::: "memory");
    __syncthreads();

    const int ar = (lane & 7) + ((lane >> 3) & 1) * 8;
    const int ac = lane >> 4;
    uint32_t Qf[8][4];
#pragma unroll
    for (int kb = 0; kb < 8; ++kb) {
        const int qrow = warp * 16 + ar;
        const uint32_t addr = sbase + FL_QS + qrow * 256 + ((((kb << 1) + ac) ^ (qrow & 7)) << 4);
        LDSM4(Qf[kb][0], Qf[kb][1], Qf[kb][2], Qf[kb][3], addr);
    }

    const int br = (lane & 7) + ((lane >> 4) & 1) * 8;
    const int bc = (lane >> 3) & 1;
    const int vr = (lane & 7) + ((lane >> 3) & 1) * 8;
    const int vc = lane >> 4;

    float acc[16][4];
#pragma unroll
    for (int dn = 0; dn < 16; ++dn)
#pragma unroll
        for (int u = 0; u < 4; ++u) acc[dn][u] = 0.f;
    float mrow[2] = {-1e30f, -1e30f};
    float lrow[2] = {0.f, 0.f};

    for (int kt = 0; kt < 32; ++kt) {
        asm volatile("cp.async.wait_group 0;" ::: "memory");
        __syncthreads();
        if (kt + 1 < 32) {
            const int row = tid >> 2;
            const int cb = (tid & 3) * 4;
            char* st = sm + FL_STAGE0 + ((kt + 1) & 1) * FL_STAGEB;
            const char* srcK = (const char*)(kh + ((long)g * T_SEQ + (kt + 1) * 64 + row) * 128);
            const char* srcV = (const char*)(vh + ((long)g * T_SEQ + (kt + 1) * 64 + row) * 128);
#pragma unroll
            for (int c = 0; c < 4; ++c) {
                const int chunk = cb + c;
                const int sw = row * 256 + ((chunk ^ (row & 7)) << 4);
                cp_async16(st + sw, srcK + chunk * 16);
                cp_async16(st + 16384 + sw, srcV + chunk * 16);
            }
            CP_COMMIT();
        }
        const uint32_t Ks = sbase + FL_STAGE0 + (kt & 1) * FL_STAGEB;
        const uint32_t Vs = Ks + 16384;

        float sacc[8][4];
#pragma unroll
        for (int j = 0; j < 8; ++j)
#pragma unroll
            for (int u = 0; u < 4; ++u) sacc[j][u] = 0.f;
#pragma unroll
        for (int kb = 0; kb < 8; ++kb) {
            uint32_t Bf[4][4];
#pragma unroll
            for (int n16 = 0; n16 < 4; ++n16) {
                const int krow = n16 * 16 + br;
                const uint32_t addr = Ks + krow * 256 + ((((kb << 1) + bc) ^ (krow & 7)) << 4);
                LDSM4(Bf[n16][0], Bf[n16][1], Bf[n16][2], Bf[n16][3], addr);
            }
#pragma unroll
            for (int nt = 0; nt < 8; ++nt)
                mma_fp16(sacc[nt], Qf[kb], Bf[nt >> 1][(nt & 1) * 2], Bf[nt >> 1][(nt & 1) * 2 + 1]);
        }

#pragma unroll
        for (int rh = 0; rh < 2; ++rh) {
            float tmax = -1e30f;
#pragma unroll
            for (int j = 0; j < 8; ++j)
                tmax = fmaxf(tmax, fmaxf(sacc[j][rh * 2], sacc[j][rh * 2 + 1]));
            tmax = fmaxf(tmax, __shfl_xor_sync(0xffffffffu, tmax, 1));
            tmax = fmaxf(tmax, __shfl_xor_sync(0xffffffffu, tmax, 2));
            const float mnew = fmaxf(mrow[rh], tmax);
            const float corr = exp2f(mrow[rh] - mnew);
            float psum = 0.f;
#pragma unroll
            for (int j = 0; j < 8; ++j) {
                const float p0 = exp2f(sacc[j][rh * 2] - mnew);
                const float p1 = exp2f(sacc[j][rh * 2 + 1] - mnew);
                sacc[j][rh * 2] = p0;
                sacc[j][rh * 2 + 1] = p1;
                psum += p0 + p1;
            }
            psum += __shfl_xor_sync(0xffffffffu, psum, 1);
            psum += __shfl_xor_sync(0xffffffffu, psum, 2);
            lrow[rh] = lrow[rh] * corr + psum;
            mrow[rh] = mnew;
#pragma unroll
            for (int dn = 0; dn < 16; ++dn) {
                acc[dn][rh * 2] *= corr;
                acc[dn][rh * 2 + 1] *= corr;
            }
        }

        uint32_t Pa[4][4];
#pragma unroll
        for (int t = 0; t < 4; ++t) {
            Pa[t][0] = pack_f2h(sacc[2 * t][0], sacc[2 * t][1]);
            Pa[t][1] = pack_f2h(sacc[2 * t][2], sacc[2 * t][3]);
            Pa[t][2] = pack_f2h(sacc[2 * t + 1][0], sacc[2 * t + 1][1]);
            Pa[t][3] = pack_f2h(sacc[2 * t + 1][2], sacc[2 * t + 1][3]);
        }

#pragma unroll
        for (int t = 0; t < 4; ++t) {
            const int vrow = t * 16 + vr;
#pragma unroll
            for (int dn16 = 0; dn16 < 8; ++dn16) {
                uint32_t Vt[4];
                const uint32_t addr = Vs + vrow * 256 + ((((dn16 << 1) + vc) ^ (vrow & 7)) << 4);
                LDSM4T(Vt[0], Vt[1], Vt[2], Vt[3], addr);
                mma_fp16(acc[dn16 * 2],     Pa[t], Vt[0], Vt[1]);
                mma_fp16(acc[dn16 * 2 + 1], Pa[t], Vt[2], Vt[3]);
            }
        }
    }

    const int gi = lane >> 2;
    const int ci = lane & 3;
    const float il0 = 1.f / lrow[0];
    const float il1 = 1.f / lrow[1];
    const long row0 = (long)qb * 128 + warp * 16 + gi;
    const long row1 = row0 + 8;
#pragma unroll
    for (int dn = 0; dn < 16; ++dn) {
        const long col = h * 128 + dn * 8 + ci * 2;
        *(uint32_t*)(y + row0 * C_EMB + col) = pack_f2h(acc[dn][0] * il0, acc[dn][1] * il0);
        *(uint32_t*)(y + row1 * C_EMB + col) = pack_f2h(acc[dn][2] * il1, acc[dn][3] * il1);
    }
}

// ---------------- host launcher ----------------
extern "C" void kernel_launch(void* const* d_in, const int* in_sizes, int n_in,
                              void* d_out, int out_size) {
    const float* x       = (const float*)d_in[0];
    const float* cosb    = (const float*)d_in[1];
    const float* sinb    = (const float*)d_in[2];
    const float* norm1_w = (const float*)d_in[3];
    const float* norm2_w = (const float*)d_in[4];
    const float* attn_w  = (const float*)d_in[5];
    const float* proj_w  = (const float*)d_in[6];
    const float* scale_w = (const float*)d_in[7];
    const float* scale_b = (const float*)d_in[8];
    const float* gate_w  = (const float*)d_in[9];
    const float* up_w    = (const float*)d_in[10];
    const float* down_w  = (const float*)d_in[11];
    float* out = (float*)d_out;

    float *scale_t, *resid, *gate;
    cudaGetSymbolAddress((void**)&scale_t, g_scale_t);
    cudaGetSymbolAddress((void**)&resid, g_resid);
    cudaGetSymbolAddress((void**)&gate, g_gate);

    __half *wq, *ws, *wp, *wg, *wu, *wd, *qkvh, *n1, *n2, *y, *hb, *qh, *kh, *vh;
    cudaGetSymbolAddress((void**)&wq, g_wq);
    cudaGetSymbolAddress((void**)&ws, g_ws);
    cudaGetSymbolAddress((void**)&wp, g_wp);
    cudaGetSymbolAddress((void**)&wg, g_wg);
    cudaGetSymbolAddress((void**)&wu, g_wu);
    cudaGetSymbolAddress((void**)&wd, g_wd);
    cudaGetSymbolAddress((void**)&qkvh, g_qkvh);
    cudaGetSymbolAddress((void**)&n1, g_n1);
    cudaGetSymbolAddress((void**)&n2, g_n2);
    cudaGetSymbolAddress((void**)&y, g_y);
    cudaGetSymbolAddress((void**)&hb, g_hb);
    cudaGetSymbolAddress((void**)&qh, g_qh);
    cudaGetSymbolAddress((void**)&kh, g_kh);
    cudaGetSymbolAddress((void**)&vh, g_vh);

    cudaFuncSetAttribute(flash_mma, cudaFuncAttributeMaxDynamicSharedMemorySize, FLASH_SMEM);
    cudaFuncSetAttribute(hgemm<0, 0>, cudaFuncAttributeMaxDynamicSharedMemorySize, GEMM_SMEM);
    cudaFuncSetAttribute(hgemm<0, 1>, cudaFuncAttributeMaxDynamicSharedMemorySize, GEMM_SMEM);
    cudaFuncSetAttribute(hgemm<2, 0>, cudaFuncAttributeMaxDynamicSharedMemorySize, GEMM_SMEM);
    cudaFuncSetAttribute(hgemm<3, 1>, cudaFuncAttributeMaxDynamicSharedMemorySize, GEMM_SMEM);
    cudaFuncSetAttribute(hgemm<4, 0>, cudaFuncAttributeMaxDynamicSharedMemorySize, GEMM_SMEM);

    // lazily-created side streams + events
    static cudaStream_t s_cvt = nullptr, s_sc = nullptr;
    static cudaEvent_t evFork = nullptr, evWq = nullptr, evWs = nullptr,
                       evWp = nullptr, evWg = nullptr, evWu = nullptr, evWd = nullptr,
                       evN1 = nullptr, evScaleT = nullptr;
    if (s_cvt == nullptr) {
        cudaStreamCreateWithFlags(&s_cvt, cudaStreamNonBlocking);
        cudaStreamCreateWithFlags(&s_sc, cudaStreamNonBlocking);
        cudaEventCreateWithFlags(&evFork, cudaEventDisableTiming);
        cudaEventCreateWithFlags(&evWq, cudaEventDisableTiming);
        cudaEventCreateWithFlags(&evWs, cudaEventDisableTiming);
        cudaEventCreateWithFlags(&evWp, cudaEventDisableTiming);
        cudaEventCreateWithFlags(&evWg, cudaEventDisableTiming);
        cudaEventCreateWithFlags(&evWu, cudaEventDisableTiming);
        cudaEventCreateWithFlags(&evWd, cudaEventDisableTiming);
        cudaEventCreateWithFlags(&evN1, cudaEventDisableTiming);
        cudaEventCreateWithFlags(&evScaleT, cudaEventDisableTiming);
    }

    // fork: converts on s_cvt (DRAM-bound) overlap the tensor-bound main chain
    cudaEventRecord(evFork, 0);
    cudaStreamWaitEvent(s_cvt, evFork, 0);
    cvt_kernel<<<(QKV_N * C_EMB) / 1024, 256, 0, s_cvt>>>(attn_w, wq);
    cudaEventRecord(evWq, s_cvt);
    cvt_kernel<<<(C_EMB * C_EMB) / 1024, 256, 0, s_cvt>>>(scale_w, ws);
    cudaEventRecord(evWs, s_cvt);
    cvt_kernel<<<(C_EMB * C_EMB) / 1024, 256, 0, s_cvt>>>(proj_w, wp);
    cudaEventRecord(evWp, s_cvt);
    cvt_kernel<<<(FFN_N * C_EMB) / 1024, 256, 0, s_cvt>>>(gate_w, wg);
    cudaEventRecord(evWg, s_cvt);
    cvt_kernel<<<(FFN_N * C_EMB) / 1024, 256, 0, s_cvt>>>(up_w, wu);
    cudaEventRecord(evWu, s_cvt);
    cvt_kernel<<<(C_EMB * FFN_N) / 1024, 256, 0, s_cvt>>>(down_w, wd);
    cudaEventRecord(evWd, s_cvt);

    // main: n1 = rmsnorm(x) -> fp16
    rmsnorm_h<<<T_SEQ, 256>>>(x, norm1_w, n1);
    cudaEventRecord(evN1, 0);

    // side stream s_sc: scaling GEMM with fused scale_t reduction (EPI=4),
    // concurrent with the qkv GEMM on the main stream.
    cudaStreamWaitEvent(s_sc, evN1, 0);
    cudaStreamWaitEvent(s_sc, evWs, 0);
    hgemm<4, 0><<<dim3(C_EMB / 128, T_SEQ / 128), 256, GEMM_SMEM, s_sc>>>(
        n1, ws, scale_t, nullptr, T_SEQ, C_EMB, C_EMB, nullptr, scale_b);
    cudaEventRecord(evScaleT, s_sc);

    // main: qkv = n1 @ attn_w^T -> fp16
    cudaStreamWaitEvent(0, evWq, 0);
    hgemm<0, 1><<<dim3(QKV_N / 128, T_SEQ / 128), 256, GEMM_SMEM>>>(
        n1, wq, nullptr, qkvh, T_SEQ, QKV_N, C_EMB, nullptr, nullptr);
    // rope + prescale (needs scale_t from side stream)
    cudaStreamWaitEvent(0, evScaleT, 0);
    qkv_prep<<<dim3(T_SEQ, 8), 128>>>(qkvh, cosb, sinb, scale_t, qh, kh, vh);
    // flash attention -> y fp16
    flash_mma<<<dim3(T_SEQ / 128, N_HEAD_), 256, FLASH_SMEM>>>(qh, kh, vh, y);
    // resid = x + y @ proj_w^T (fp32)
    cudaStreamWaitEvent(0, evWp, 0);
    hgemm<2, 0><<<dim3(C_EMB / 128, T_SEQ / 128), 256, GEMM_SMEM>>>(
        y, wp, resid, nullptr, T_SEQ, C_EMB, C_EMB, x, nullptr);
    // n2 = rmsnorm(resid) -> fp16
    rmsnorm_h<<<T_SEQ, 256>>>(resid, norm2_w, n2);
    // gate = n2 @ gate_w^T (fp32)
    cudaStreamWaitEvent(0, evWg, 0);
    hgemm<0, 0><<<dim3(FFN_N / 128, T_SEQ / 128), 256, GEMM_SMEM>>>(
        n2, wg, gate, nullptr, T_SEQ, FFN_N, C_EMB, nullptr, nullptr);
    // hbuf = silu(gate) * (n2 @ up_w^T) -> fp16
    cudaStreamWaitEvent(0, evWu, 0);
    hgemm<3, 1><<<dim3(FFN_N / 128, T_SEQ / 128), 256, GEMM_SMEM>>>(
        n2, wu, nullptr, hb, T_SEQ, FFN_N, C_EMB, gate, nullptr);
    // out = resid + hbuf @ down_w^T (fp32)  (joins s_cvt via evWd)
    cudaStreamWaitEvent(0, evWd, 0);
    hgemm<2, 0><<<dim3(C_EMB / 128, T_SEQ / 128), 256, GEMM_SMEM>>>(
        hb, wd, out, nullptr, T_SEQ, C_EMB, FFN_N, resid, nullptr);
}